// round 1
// baseline (speedup 1.0000x reference)
#include <cuda_runtime.h>
#include <math.h>

#define B_  32
#define S_  512
#define D_  768
#define H_  8
#define DK_ 96
#define C_  3

// ---------------- scratch (device globals; no allocs allowed) ----------------
__device__ float g_q   [B_*H_*S_*DK_];      // 12.58M
__device__ float g_k   [B_*H_*S_*DK_];
__device__ float g_adj [(long)B_*S_*S_];    // 8.39M
__device__ float g_den [B_*S_];
__device__ float g_ax  [B_*S_*D_];
__device__ float g_t1  [B_*S_*D_];
__device__ float g_t2  [B_*S_*D_];
__device__ float g_pool[B_*D_];
__device__ float g_hid [B_*D_];

// ---------------- fast exp (avoid MUFU bottleneck) ----------------
__device__ __forceinline__ float fast_exp(float x) {
    // x <= 0 always here. exp(x) = 2^(x*log2e), clamp to avoid denormal trouble.
    float y = fmaxf(x * 1.4426950408889634f, -126.0f);
    float t = __fadd_rn(y, 12582912.0f);     // round-to-nearest-int trick
    float n = __fsub_rn(t, 12582912.0f);
    float f = __fsub_rn(y, n);               // f in [-0.5, 0.5]
    float p = 0.0013333558f;
    p = fmaf(p, f, 0.0096181291f);
    p = fmaf(p, f, 0.0555041087f);
    p = fmaf(p, f, 0.2402265070f);
    p = fmaf(p, f, 0.6931471806f);
    p = fmaf(p, f, 1.0f);
    int e = (int)n;
    return __int_as_float(__float_as_int(p) + (e << 23));
}

// ---------------- generic batched SGEMM: C = A * B (optionally B^T) ----------
// Tiles 64x64xK16, 256 threads, 4x4 microtile. Epilogue: bias, /denom, relu.
template<bool TRANSB, bool BIAS, bool RELU, bool DENOM>
__global__ __launch_bounds__(256) void sgemm(
    const float* __restrict__ A, const float* __restrict__ Bm, float* __restrict__ C,
    int M, int N, int K, long sA, long sB, long sC,
    int bdiv, int bmod,
    const float* __restrict__ bias, const float* __restrict__ denom, int dstride)
{
    __shared__ float As[16][68];
    __shared__ float Bs[16][68];

    const int z = blockIdx.z;
    A  += (long)(z / bdiv) * sA;
    Bm += (long)(bmod ? (z % bmod) : z) * sB;
    C  += (long)z * sC;
    if (DENOM) denom += (long)z * dstride;

    const int m0 = blockIdx.y * 64, n0 = blockIdx.x * 64;
    const int tid = threadIdx.x;
    const int tx = tid & 15, ty = tid >> 4;

    float acc[4][4];
#pragma unroll
    for (int i = 0; i < 4; i++)
#pragma unroll
        for (int j = 0; j < 4; j++) acc[i][j] = 0.0f;

    const int arow = tid >> 2, akq = (tid & 3) * 4;

    for (int k0 = 0; k0 < K; k0 += 16) {
        // A tile (64 x 16), transposed into smem
        float4 av = make_float4(0.f, 0.f, 0.f, 0.f);
        if (m0 + arow < M)
            av = *(const float4*)&A[(long)(m0 + arow) * K + k0 + akq];
        As[akq + 0][arow] = av.x; As[akq + 1][arow] = av.y;
        As[akq + 2][arow] = av.z; As[akq + 3][arow] = av.w;

        if (!TRANSB) {
            const int kr = tid >> 4, nq = (tid & 15) * 4;
            float4 bv = make_float4(0.f, 0.f, 0.f, 0.f);
            if (n0 + nq < N)
                bv = *(const float4*)&Bm[(long)(k0 + kr) * N + n0 + nq];
            Bs[kr][nq + 0] = bv.x; Bs[kr][nq + 1] = bv.y;
            Bs[kr][nq + 2] = bv.z; Bs[kr][nq + 3] = bv.w;
        } else {
            const int nrow = tid >> 2, kq = (tid & 3) * 4;
            float4 bv = make_float4(0.f, 0.f, 0.f, 0.f);
            if (n0 + nrow < N)
                bv = *(const float4*)&Bm[(long)(n0 + nrow) * K + k0 + kq];
            Bs[kq + 0][nrow] = bv.x; Bs[kq + 1][nrow] = bv.y;
            Bs[kq + 2][nrow] = bv.z; Bs[kq + 3][nrow] = bv.w;
        }
        __syncthreads();

#pragma unroll
        for (int kk = 0; kk < 16; kk++) {
            float4 a = *(const float4*)&As[kk][ty * 4];
            float4 b = *(const float4*)&Bs[kk][tx * 4];
            acc[0][0] = fmaf(a.x, b.x, acc[0][0]);
            acc[0][1] = fmaf(a.x, b.y, acc[0][1]);
            acc[0][2] = fmaf(a.x, b.z, acc[0][2]);
            acc[0][3] = fmaf(a.x, b.w, acc[0][3]);
            acc[1][0] = fmaf(a.y, b.x, acc[1][0]);
            acc[1][1] = fmaf(a.y, b.y, acc[1][1]);
            acc[1][2] = fmaf(a.y, b.z, acc[1][2]);
            acc[1][3] = fmaf(a.y, b.w, acc[1][3]);
            acc[2][0] = fmaf(a.z, b.x, acc[2][0]);
            acc[2][1] = fmaf(a.z, b.y, acc[2][1]);
            acc[2][2] = fmaf(a.z, b.z, acc[2][2]);
            acc[2][3] = fmaf(a.z, b.w, acc[2][3]);
            acc[3][0] = fmaf(a.w, b.x, acc[3][0]);
            acc[3][1] = fmaf(a.w, b.y, acc[3][1]);
            acc[3][2] = fmaf(a.w, b.z, acc[3][2]);
            acc[3][3] = fmaf(a.w, b.w, acc[3][3]);
        }
        __syncthreads();
    }

#pragma unroll
    for (int i = 0; i < 4; i++) {
        int m = m0 + ty * 4 + i;
        if (m >= M) continue;
        float dv = 1.0f;
        if (DENOM) dv = denom[m];
#pragma unroll
        for (int j = 0; j < 4; j++) {
            int n = n0 + tx * 4 + j;
            if (n < N) {
                float v = acc[i][j];
                if (BIAS)  v += bias[n];
                if (DENOM) v = v / dv;
                if (RELU)  v = fmaxf(v, 0.0f);
                C[(long)m * N + n] = v;
            }
        }
    }
}

// ---------------- fused scores->softmax->head-mean adjacency ----------------
// One block = (batch b, 32-row tile). acc[64] registers hold head-mean tile.
__global__ __launch_bounds__(256) void adj_kernel(
    const float* __restrict__ q, const float* __restrict__ k,
    const float* __restrict__ fmask,
    float* __restrict__ adj, float* __restrict__ denom)
{
    extern __shared__ float sm[];
    float* sQT    = sm;                 // [96][36]
    float* sKT    = sQT + 96 * 36;      // [96][68]
    float* sS     = sKT + 96 * 68;      // [32][516]
    float* sScale = sS + 32 * 516;      // [32]
    float* sFr    = sScale + 32;        // [32]
    float* sFm    = sFr + 32;           // [512]

    const int b   = blockIdx.y;
    const int r0  = blockIdx.x * 32;
    const int tid = threadIdx.x;
    const int ty  = tid >> 5;           // 0..7 row group (warp-uniform)
    const int tx  = tid & 31;           // col thread

    if (tid < 32) sFr[tid] = fmask[b * S_ + r0 + tid];
    for (int i = tid; i < S_; i += 256) sFm[i] = fmask[b * S_ + i];

    float acc[64];
#pragma unroll
    for (int i = 0; i < 64; i++) acc[i] = 0.0f;

    const float rs = 0.10206207261596577f;  // 1/sqrt(96)

    for (int h = 0; h < H_; h++) {
        __syncthreads();  // acc pass (reads sS) done; safe to reload tiles
        // load Q tile 32x96 -> sQT[kk][r]
        {
            const float* qp = q + (((long)b * H_ + h) * S_ + r0) * DK_;
            for (int i = tid; i < 32 * 24; i += 256) {
                int r = i / 24, kq = (i % 24) * 4;
                float4 v = *(const float4*)&qp[r * DK_ + kq];
                sQT[(kq + 0) * 36 + r] = v.x; sQT[(kq + 1) * 36 + r] = v.y;
                sQT[(kq + 2) * 36 + r] = v.z; sQT[(kq + 3) * 36 + r] = v.w;
            }
        }
        for (int tc = 0; tc < 8; tc++) {
            __syncthreads();
            // load K chunk 64x96 -> sKT[kk][t]
            {
                const float* kp = k + (((long)b * H_ + h) * S_ + tc * 64) * DK_;
                for (int i = tid; i < 64 * 24; i += 256) {
                    int t = i / 24, kq = (i % 24) * 4;
                    float4 v = *(const float4*)&kp[t * DK_ + kq];
                    sKT[(kq + 0) * 68 + t] = v.x; sKT[(kq + 1) * 68 + t] = v.y;
                    sKT[(kq + 2) * 68 + t] = v.z; sKT[(kq + 3) * 68 + t] = v.w;
                }
            }
            __syncthreads();
            // 32x64 score tile: microtile 4 rows x 2 cols per thread
            float sa[4][2];
#pragma unroll
            for (int i = 0; i < 4; i++) { sa[i][0] = 0.f; sa[i][1] = 0.f; }
#pragma unroll 8
            for (int kk = 0; kk < 96; kk++) {
                float4 a  = *(const float4*)&sQT[kk * 36 + ty * 4];
                float2 bb = *(const float2*)&sKT[kk * 68 + tx * 2];
                sa[0][0] = fmaf(a.x, bb.x, sa[0][0]);
                sa[0][1] = fmaf(a.x, bb.y, sa[0][1]);
                sa[1][0] = fmaf(a.y, bb.x, sa[1][0]);
                sa[1][1] = fmaf(a.y, bb.y, sa[1][1]);
                sa[2][0] = fmaf(a.z, bb.x, sa[2][0]);
                sa[2][1] = fmaf(a.z, bb.y, sa[2][1]);
                sa[3][0] = fmaf(a.w, bb.x, sa[3][0]);
                sa[3][1] = fmaf(a.w, bb.y, sa[3][1]);
            }
#pragma unroll
            for (int i = 0; i < 4; i++) {
                int r = ty * 4 + i;
                float fr = sFr[r];
#pragma unroll
                for (int j = 0; j < 2; j++) {
                    int t = tc * 64 + tx * 2 + j;
                    float v = sa[i][j] * rs;
                    if (fr * sFm[t] == 0.0f) v = -1e9f;
                    sS[r * 516 + t] = v;
                }
            }
        }
        __syncthreads();
        // softmax: 8 threads per row
        {
            int r = tid >> 3, lane = tid & 7;
            float m = -INFINITY;
            for (int t = lane; t < S_; t += 8) m = fmaxf(m, sS[r * 516 + t]);
            m = fmaxf(m, __shfl_xor_sync(0xffffffffu, m, 1));
            m = fmaxf(m, __shfl_xor_sync(0xffffffffu, m, 2));
            m = fmaxf(m, __shfl_xor_sync(0xffffffffu, m, 4));
            float s = 0.0f;
            for (int t = lane; t < S_; t += 8) {
                float e = fast_exp(sS[r * 516 + t] - m);
                sS[r * 516 + t] = e;
                s += e;
            }
            s += __shfl_xor_sync(0xffffffffu, s, 1);
            s += __shfl_xor_sync(0xffffffffu, s, 2);
            s += __shfl_xor_sync(0xffffffffu, s, 4);
            if (lane == 0) sScale[r] = 1.0f / (8.0f * s);   // fold head-mean
        }
        __syncthreads();
        // accumulate normalized attention into register tile
#pragma unroll
        for (int i = 0; i < 64; i++) {
            int flat = tid + 256 * i;
            int r = flat >> 9, t = flat & 511;
            acc[i] = fmaf(sS[r * 516 + t], sScale[r], acc[i]);
        }
    }

    // write adj (diag -> 1) and denom = 3 - mean_diag
    long base = ((long)b * S_ + r0) * S_;
#pragma unroll
    for (int i = 0; i < 64; i++) {
        int flat = tid + 256 * i;
        int r = flat >> 9, t = flat & 511;
        int sg = r0 + r;
        float v = acc[i];
        if (t == sg) {
            denom[b * S_ + sg] = 3.0f - v;
            v = 1.0f;
        }
        adj[base + (long)r * S_ + t] = v;
    }
}

// ---------------- aspect max-pool ----------------
__global__ void pool_kernel(const float* __restrict__ tok,
                            const int* __restrict__ am,
                            float* __restrict__ pool)
{
    int d = blockIdx.x * 256 + threadIdx.x;
    int b = blockIdx.y;
    if (d >= D_) return;
    const float* tp = tok + (long)b * S_ * D_;
    const int*   ap = am + b * S_;
    float m = -10000.0f;
    for (int s = 0; s < S_; s++) {
        float v = (ap[s] == 1) ? tp[(long)s * D_ + d] : -10000.0f;
        m = fmaxf(m, v);
    }
    pool[b * D_ + d] = m;
}

// ---------------- FFN2 + output assembly (preds_ then preds) ----------------
__global__ void ffn2_kernel(const float* __restrict__ h,
                            const float* __restrict__ w2,
                            const float* __restrict__ b2,
                            const float* __restrict__ pool,
                            float* __restrict__ out)
{
    int bid = blockIdx.x;
    if (bid < 96) {                         // copy preds (B*D floats)
        int idx = bid * 256 + threadIdx.x;
        out[B_ * C_ + idx] = pool[idx];
    } else {                                // preds_ = h @ W2^T + b2
        int t = threadIdx.x;
        if (t < B_ * C_) {
            int b = t / C_, c = t % C_;
            const float* hp = h + b * D_;
            const float* wp = w2 + c * D_;
            float s = b2[c];
            for (int d = 0; d < D_; d++) s = fmaf(hp[d], wp[d], s);
            out[b * C_ + c] = s;
        }
    }
}

// ---------------- orchestration ----------------
extern "C" void kernel_launch(void* const* d_in, const int* in_sizes, int n_in,
                              void* d_out, int out_size)
{
    const float* x     = (const float*)d_in[0];
    const float* fmask = (const float*)d_in[1];
    const int*   amask = (const int*)  d_in[2];
    const float* wq    = (const float*)d_in[3];
    const float* wk    = (const float*)d_in[4];
    const float* gw    = (const float*)d_in[5];
    const float* gb    = (const float*)d_in[6];
    const float* w1    = (const float*)d_in[7];
    const float* b1    = (const float*)d_in[8];
    const float* w2    = (const float*)d_in[9];
    const float* b2    = (const float*)d_in[10];
    float* out = (float*)d_out;

    float *pq, *pk, *padj, *pden, *pax, *pt1, *pt2, *ppool, *phid;
    cudaGetSymbolAddress((void**)&pq,    g_q);
    cudaGetSymbolAddress((void**)&pk,    g_k);
    cudaGetSymbolAddress((void**)&padj,  g_adj);
    cudaGetSymbolAddress((void**)&pden,  g_den);
    cudaGetSymbolAddress((void**)&pax,   g_ax);
    cudaGetSymbolAddress((void**)&pt1,   g_t1);
    cudaGetSymbolAddress((void**)&pt2,   g_t2);
    cudaGetSymbolAddress((void**)&ppool, g_pool);
    cudaGetSymbolAddress((void**)&phid,  g_hid);

    // Q/K projections: per (b,h) GEMM 512x96x768
    {
        dim3 g(2, 8, B_ * H_);
        sgemm<false,false,false,false><<<g, 256>>>(
            x, wq, pq, S_, DK_, D_,
            (long)S_ * D_, (long)D_ * DK_, (long)S_ * DK_, H_, H_,
            nullptr, nullptr, 0);
        sgemm<false,false,false,false><<<g, 256>>>(
            x, wk, pk, S_, DK_, D_,
            (long)S_ * D_, (long)D_ * DK_, (long)S_ * DK_, H_, H_,
            nullptr, nullptr, 0);
    }

    // fused scores -> softmax -> head-mean -> adjacency (+denom)
    {
        const int smem = (96*36 + 96*68 + 32*516 + 32 + 32 + 512) * 4; // 108288
        cudaFuncSetAttribute(adj_kernel,
                             cudaFuncAttributeMaxDynamicSharedMemorySize, smem);
        adj_kernel<<<dim3(16, B_), 256, smem>>>(pq, pk, fmask, padj, pden);
    }

    // GCN layers
    {
        dim3 g(12, 8, B_);
        // layer 0: Ax = adj @ x
        sgemm<false,false,false,false><<<g, 256>>>(
            padj, x, pax, S_, D_, S_,
            (long)S_ * S_, (long)S_ * D_, (long)S_ * D_, 1, 0,
            nullptr, nullptr, 0);
        // t1 = relu((Ax @ W0^T + b0) / denom)
        sgemm<true,true,true,true><<<g, 256>>>(
            pax, gw, pt1, S_, D_, D_,
            (long)S_ * D_, 0L, (long)S_ * D_, 1, 1,
            gb, pden, S_);
        // layer 1: Ax = adj @ t1
        sgemm<false,false,false,false><<<g, 256>>>(
            padj, pt1, pax, S_, D_, S_,
            (long)S_ * S_, (long)S_ * D_, (long)S_ * D_, 1, 0,
            nullptr, nullptr, 0);
        // t2 = relu((Ax @ W1^T + b1) / denom)
        sgemm<true,true,true,true><<<g, 256>>>(
            pax, gw + (long)D_ * D_, pt2, S_, D_, D_,
            (long)S_ * D_, 0L, (long)S_ * D_, 1, 1,
            gb + D_, pden, S_);
    }

    // aspect max-pool -> preds
    pool_kernel<<<dim3(3, B_), 256>>>(pt2, amask, ppool);

    // FFN1: h = relu(preds @ W1^T + b1)
    sgemm<true,true,true,false><<<dim3(12, 1, 1), 256>>>(
        ppool, w1, phid, B_, D_, D_,
        0L, 0L, 0L, 1, 1, b1, nullptr, 0);

    // FFN2 + output: [preds_ (B*C) | preds (B*D)]
    ffn2_kernel<<<97, 256>>>(phid, w2, b2, ppool, out);
}

// round 2
// speedup vs baseline: 1.2237x; 1.2237x over previous
#include <cuda_runtime.h>
#include <math.h>

#define B_  32
#define S_  512
#define D_  768
#define H_  8
#define DK_ 96
#define C_  3
#define QKW 1536   // fused q|k width

// ---------------- scratch (device globals; no allocs allowed) ----------------
__device__ float g_qk  [(long)B_*S_*QKW];   // fused q|k projections, 100.7MB
__device__ float g_wqk [D_*QKW];            // transposed/concat weights
__device__ float g_adj [(long)B_*S_*S_];
__device__ float g_den [B_*S_];
__device__ float g_ax  [B_*S_*D_];
__device__ float g_t1  [B_*S_*D_];
__device__ float g_t2  [B_*S_*D_];
__device__ float g_pool[B_*D_];
__device__ float g_hid [B_*D_];

// ---------------- fast exp (avoid MUFU bottleneck) ----------------
__device__ __forceinline__ float fast_exp(float x) {
    float y = fmaxf(x * 1.4426950408889634f, -126.0f);
    float t = __fadd_rn(y, 12582912.0f);
    float n = __fsub_rn(t, 12582912.0f);
    float f = __fsub_rn(y, n);
    float p = 0.0013333558f;
    p = fmaf(p, f, 0.0096181291f);
    p = fmaf(p, f, 0.0555041087f);
    p = fmaf(p, f, 0.2402265070f);
    p = fmaf(p, f, 0.6931471806f);
    p = fmaf(p, f, 1.0f);
    int e = (int)n;
    return __int_as_float(__float_as_int(p) + (e << 23));
}

// ---------------- weight concat/transpose: [H,D,DK]x2 -> [D, H*DK | H*DK] ----
__global__ void wqk_transpose(const float* __restrict__ wq,
                              const float* __restrict__ wk,
                              float* __restrict__ out)
{
    int idx = blockIdx.x * 256 + threadIdx.x;
    if (idx >= H_ * D_ * DK_) return;
    int h = idx / (D_ * DK_);
    int r = idx % (D_ * DK_);
    int d = r / DK_, j = r % DK_;
    out[(long)d * QKW + h * DK_ + j]       = wq[idx];
    out[(long)d * QKW + D_ + h * DK_ + j]  = wk[idx];
}

// ---------------- big SGEMM: 128x128 tile, 8x8 micro, double-buffered -------
// Requires M%128==0, N%128==0, K%8==0 (true for all call sites).
template<bool TRANSB, bool BIAS, bool RELU, bool DENOM>
__global__ __launch_bounds__(256) void gemm128(
    const float* __restrict__ A, const float* __restrict__ Bm, float* __restrict__ C,
    int M, int N, int K, long sA, long sB, long sC, int bmod,
    const float* __restrict__ bias, const float* __restrict__ denom, int dstride)
{
    __shared__ float As[2][8][132];
    __shared__ float Bs[2][8][132];

    const int z = blockIdx.z;
    A  += (long)z * sA;
    Bm += (long)(bmod ? 0 : z) * sB;
    C  += (long)z * sC;
    if (DENOM) denom += (long)z * dstride;

    const int m0 = blockIdx.y * 128, n0 = blockIdx.x * 128;
    const int tid = threadIdx.x;
    const int tx = tid & 15, ty = tid >> 4;

    const int lr = tid >> 1;           // 0..127
    const int lk = (tid & 1) * 4;      // 0 or 4
    const int bk = tid >> 5;           // 0..7
    const int bn = (tid & 31) * 4;

    float4 ra, rb;
    ra = *(const float4*)&A[(long)(m0 + lr) * K + lk];
    if (TRANSB) rb = *(const float4*)&Bm[(long)(n0 + lr) * K + lk];
    else        rb = *(const float4*)&Bm[(long)bk * N + n0 + bn];

    As[0][lk+0][lr] = ra.x; As[0][lk+1][lr] = ra.y;
    As[0][lk+2][lr] = ra.z; As[0][lk+3][lr] = ra.w;
    if (TRANSB) {
        Bs[0][lk+0][lr] = rb.x; Bs[0][lk+1][lr] = rb.y;
        Bs[0][lk+2][lr] = rb.z; Bs[0][lk+3][lr] = rb.w;
    } else {
        *(float4*)&Bs[0][bk][bn] = rb;
    }
    __syncthreads();

    float acc[8][8];
#pragma unroll
    for (int i = 0; i < 8; i++)
#pragma unroll
        for (int j = 0; j < 8; j++) acc[i][j] = 0.0f;

    int buf = 0;
    const int nk = K >> 3;
    for (int it = 1; it < nk; it++) {
        const int k0 = it * 8;
        ra = *(const float4*)&A[(long)(m0 + lr) * K + k0 + lk];
        if (TRANSB) rb = *(const float4*)&Bm[(long)(n0 + lr) * K + k0 + lk];
        else        rb = *(const float4*)&Bm[(long)(k0 + bk) * N + n0 + bn];

#pragma unroll
        for (int kk = 0; kk < 8; kk++) {
            float4 a0 = *(const float4*)&As[buf][kk][ty*8];
            float4 a1 = *(const float4*)&As[buf][kk][ty*8+4];
            float4 b0 = *(const float4*)&Bs[buf][kk][tx*8];
            float4 b1 = *(const float4*)&Bs[buf][kk][tx*8+4];
            float av[8] = {a0.x,a0.y,a0.z,a0.w,a1.x,a1.y,a1.z,a1.w};
            float bv[8] = {b0.x,b0.y,b0.z,b0.w,b1.x,b1.y,b1.z,b1.w};
#pragma unroll
            for (int i = 0; i < 8; i++)
#pragma unroll
                for (int j = 0; j < 8; j++)
                    acc[i][j] = fmaf(av[i], bv[j], acc[i][j]);
        }
        const int nb = buf ^ 1;
        As[nb][lk+0][lr] = ra.x; As[nb][lk+1][lr] = ra.y;
        As[nb][lk+2][lr] = ra.z; As[nb][lk+3][lr] = ra.w;
        if (TRANSB) {
            Bs[nb][lk+0][lr] = rb.x; Bs[nb][lk+1][lr] = rb.y;
            Bs[nb][lk+2][lr] = rb.z; Bs[nb][lk+3][lr] = rb.w;
        } else {
            *(float4*)&Bs[nb][bk][bn] = rb;
        }
        __syncthreads();
        buf = nb;
    }
    // last tile
#pragma unroll
    for (int kk = 0; kk < 8; kk++) {
        float4 a0 = *(const float4*)&As[buf][kk][ty*8];
        float4 a1 = *(const float4*)&As[buf][kk][ty*8+4];
        float4 b0 = *(const float4*)&Bs[buf][kk][tx*8];
        float4 b1 = *(const float4*)&Bs[buf][kk][tx*8+4];
        float av[8] = {a0.x,a0.y,a0.z,a0.w,a1.x,a1.y,a1.z,a1.w};
        float bv[8] = {b0.x,b0.y,b0.z,b0.w,b1.x,b1.y,b1.z,b1.w};
#pragma unroll
        for (int i = 0; i < 8; i++)
#pragma unroll
            for (int j = 0; j < 8; j++)
                acc[i][j] = fmaf(av[i], bv[j], acc[i][j]);
    }

#pragma unroll
    for (int i = 0; i < 8; i++) {
        int m = m0 + ty * 8 + i;
        float dv = DENOM ? denom[m] : 1.0f;
        float4 o0, o1;
        float* po = (float*)&o0;
#pragma unroll
        for (int j = 0; j < 8; j++) {
            int n = n0 + tx * 8 + j;
            float v = acc[i][j];
            if (BIAS)  v += bias[n];
            if (DENOM) v = v / dv;
            if (RELU)  v = fmaxf(v, 0.0f);
            ((float*)&o0)[0]; // no-op to keep compiler calm
            if (j < 4) ((float*)&o0)[j] = v; else ((float*)&o1)[j-4] = v;
        }
        (void)po;
        *(float4*)&C[(long)m * N + n0 + tx*8]     = o0;
        *(float4*)&C[(long)m * N + n0 + tx*8 + 4] = o1;
    }
}

// ---------------- small guarded SGEMM (FFN1 only: M=32) ----------------------
template<bool TRANSB, bool BIAS, bool RELU>
__global__ __launch_bounds__(256) void sgemm_small(
    const float* __restrict__ A, const float* __restrict__ Bm, float* __restrict__ C,
    int M, int N, int K, const float* __restrict__ bias)
{
    __shared__ float As[16][68];
    __shared__ float Bs[16][68];
    const int m0 = blockIdx.y * 64, n0 = blockIdx.x * 64;
    const int tid = threadIdx.x;
    const int tx = tid & 15, ty = tid >> 4;
    float acc[4][4];
#pragma unroll
    for (int i = 0; i < 4; i++)
#pragma unroll
        for (int j = 0; j < 4; j++) acc[i][j] = 0.0f;
    const int arow = tid >> 2, akq = (tid & 3) * 4;
    for (int k0 = 0; k0 < K; k0 += 16) {
        float4 av = make_float4(0.f,0.f,0.f,0.f);
        if (m0 + arow < M)
            av = *(const float4*)&A[(long)(m0 + arow) * K + k0 + akq];
        As[akq+0][arow]=av.x; As[akq+1][arow]=av.y;
        As[akq+2][arow]=av.z; As[akq+3][arow]=av.w;
        if (!TRANSB) {
            const int kr = tid >> 4, nq = (tid & 15) * 4;
            float4 bv = make_float4(0.f,0.f,0.f,0.f);
            if (n0 + nq < N)
                bv = *(const float4*)&Bm[(long)(k0+kr)*N + n0 + nq];
            Bs[kr][nq+0]=bv.x; Bs[kr][nq+1]=bv.y; Bs[kr][nq+2]=bv.z; Bs[kr][nq+3]=bv.w;
        } else {
            const int nrow = tid >> 2, kq = (tid & 3) * 4;
            float4 bv = make_float4(0.f,0.f,0.f,0.f);
            if (n0 + nrow < N)
                bv = *(const float4*)&Bm[(long)(n0+nrow)*K + k0 + kq];
            Bs[kq+0][nrow]=bv.x; Bs[kq+1][nrow]=bv.y; Bs[kq+2][nrow]=bv.z; Bs[kq+3][nrow]=bv.w;
        }
        __syncthreads();
#pragma unroll
        for (int kk = 0; kk < 16; kk++) {
            float4 a = *(const float4*)&As[kk][ty*4];
            float4 b = *(const float4*)&Bs[kk][tx*4];
            acc[0][0]=fmaf(a.x,b.x,acc[0][0]); acc[0][1]=fmaf(a.x,b.y,acc[0][1]);
            acc[0][2]=fmaf(a.x,b.z,acc[0][2]); acc[0][3]=fmaf(a.x,b.w,acc[0][3]);
            acc[1][0]=fmaf(a.y,b.x,acc[1][0]); acc[1][1]=fmaf(a.y,b.y,acc[1][1]);
            acc[1][2]=fmaf(a.y,b.z,acc[1][2]); acc[1][3]=fmaf(a.y,b.w,acc[1][3]);
            acc[2][0]=fmaf(a.z,b.x,acc[2][0]); acc[2][1]=fmaf(a.z,b.y,acc[2][1]);
            acc[2][2]=fmaf(a.z,b.z,acc[2][2]); acc[2][3]=fmaf(a.z,b.w,acc[2][3]);
            acc[3][0]=fmaf(a.w,b.x,acc[3][0]); acc[3][1]=fmaf(a.w,b.y,acc[3][1]);
            acc[3][2]=fmaf(a.w,b.z,acc[3][2]); acc[3][3]=fmaf(a.w,b.w,acc[3][3]);
        }
        __syncthreads();
    }
#pragma unroll
    for (int i = 0; i < 4; i++) {
        int m = m0 + ty*4 + i;
        if (m >= M) continue;
#pragma unroll
        for (int j = 0; j < 4; j++) {
            int n = n0 + tx*4 + j;
            if (n < N) {
                float v = acc[i][j];
                if (BIAS) v += bias[n];
                if (RELU) v = fmaxf(v, 0.0f);
                C[(long)m * N + n] = v;
            }
        }
    }
}

// ---------------- fused scores->softmax->head-mean adjacency ----------------
__global__ __launch_bounds__(256) void adj_kernel(
    const float* __restrict__ qk, const float* __restrict__ fmask,
    float* __restrict__ adj, float* __restrict__ denom)
{
    extern __shared__ float sm[];
    float* sQT    = sm;                  // [96][36]
    float* sKT    = sQT + 96 * 36;       // [96][132]
    float* sS     = sKT + 96 * 132;      // [32][516]
    float* sScale = sS + 32 * 516;       // [32]
    float* sFr    = sScale + 32;         // [32]
    float* sFm    = sFr + 32;            // [512]

    const int b   = blockIdx.y;
    const int r0  = blockIdx.x * 32;
    const int tid = threadIdx.x;
    const int ty  = tid >> 5;            // 0..7, warp-uniform
    const int tx  = tid & 31;

    if (tid < 32) sFr[tid] = fmask[b * S_ + r0 + tid];
    for (int i = tid; i < S_; i += 256) sFm[i] = fmask[b * S_ + i];

    float acc[64];
#pragma unroll
    for (int i = 0; i < 64; i++) acc[i] = 0.0f;

    const float rs = 0.10206207261596577f;   // 1/sqrt(96)
    const float* qb = qk + (long)(b * S_ + r0) * QKW;
    const float* kb = qk + (long)b * S_ * QKW + D_;   // k half

    for (int h = 0; h < H_; h++) {
        __syncthreads();
        // Q tile 32x96 -> sQT[kk][r]
        for (int i = tid; i < 32 * 24; i += 256) {
            int r = i / 24, kq = (i % 24) * 4;
            float4 v = *(const float4*)&qb[(long)r * QKW + h * DK_ + kq];
            sQT[(kq+0)*36+r]=v.x; sQT[(kq+1)*36+r]=v.y;
            sQT[(kq+2)*36+r]=v.z; sQT[(kq+3)*36+r]=v.w;
        }
        for (int tc = 0; tc < 4; tc++) {
            __syncthreads();
            // K chunk 128x96 -> sKT[kk][t]
            for (int i = tid; i < 128 * 24; i += 256) {
                int t = i / 24, kq = (i % 24) * 4;
                float4 v = *(const float4*)&kb[(long)(tc*128 + t) * QKW + h * DK_ + kq];
                sKT[(kq+0)*132+t]=v.x; sKT[(kq+1)*132+t]=v.y;
                sKT[(kq+2)*132+t]=v.z; sKT[(kq+3)*132+t]=v.w;
            }
            __syncthreads();
            float sa[4][4];
#pragma unroll
            for (int i = 0; i < 4; i++)
#pragma unroll
                for (int j = 0; j < 4; j++) sa[i][j] = 0.0f;
#pragma unroll 8
            for (int kk = 0; kk < 96; kk++) {
                float4 a  = *(const float4*)&sQT[kk * 36  + ty * 4];
                float4 bb = *(const float4*)&sKT[kk * 132 + tx * 4];
                sa[0][0]=fmaf(a.x,bb.x,sa[0][0]); sa[0][1]=fmaf(a.x,bb.y,sa[0][1]);
                sa[0][2]=fmaf(a.x,bb.z,sa[0][2]); sa[0][3]=fmaf(a.x,bb.w,sa[0][3]);
                sa[1][0]=fmaf(a.y,bb.x,sa[1][0]); sa[1][1]=fmaf(a.y,bb.y,sa[1][1]);
                sa[1][2]=fmaf(a.y,bb.z,sa[1][2]); sa[1][3]=fmaf(a.y,bb.w,sa[1][3]);
                sa[2][0]=fmaf(a.z,bb.x,sa[2][0]); sa[2][1]=fmaf(a.z,bb.y,sa[2][1]);
                sa[2][2]=fmaf(a.z,bb.z,sa[2][2]); sa[2][3]=fmaf(a.z,bb.w,sa[2][3]);
                sa[3][0]=fmaf(a.w,bb.x,sa[3][0]); sa[3][1]=fmaf(a.w,bb.y,sa[3][1]);
                sa[3][2]=fmaf(a.w,bb.z,sa[3][2]); sa[3][3]=fmaf(a.w,bb.w,sa[3][3]);
            }
#pragma unroll
            for (int i = 0; i < 4; i++) {
                int r = ty * 4 + i;
                float fr = sFr[r];
                float4 o;
                int t0 = tc * 128 + tx * 4;
#pragma unroll
                for (int j = 0; j < 4; j++) {
                    float v = sa[i][j] * rs;
                    if (fr * sFm[t0 + j] == 0.0f) v = -1e9f;
                    ((float*)&o)[j] = v;
                }
                *(float4*)&sS[r * 516 + t0] = o;
            }
        }
        __syncthreads();
        // softmax: 8 threads per row
        {
            int r = tid >> 3, lane = tid & 7;
            float m = -INFINITY;
            for (int t = lane; t < S_; t += 8) m = fmaxf(m, sS[r * 516 + t]);
            m = fmaxf(m, __shfl_xor_sync(0xffffffffu, m, 1));
            m = fmaxf(m, __shfl_xor_sync(0xffffffffu, m, 2));
            m = fmaxf(m, __shfl_xor_sync(0xffffffffu, m, 4));
            float s = 0.0f;
            for (int t = lane; t < S_; t += 8) {
                float e = fast_exp(sS[r * 516 + t] - m);
                sS[r * 516 + t] = e;
                s += e;
            }
            s += __shfl_xor_sync(0xffffffffu, s, 1);
            s += __shfl_xor_sync(0xffffffffu, s, 2);
            s += __shfl_xor_sync(0xffffffffu, s, 4);
            if (lane == 0) sScale[r] = 1.0f / (8.0f * s);
        }
        __syncthreads();
#pragma unroll
        for (int i = 0; i < 64; i++) {
            int flat = tid + 256 * i;
            int r = flat >> 9, t = flat & 511;
            acc[i] = fmaf(sS[r * 516 + t], sScale[r], acc[i]);
        }
    }

    long base = ((long)b * S_ + r0) * S_;
#pragma unroll
    for (int i = 0; i < 64; i++) {
        int flat = tid + 256 * i;
        int r = flat >> 9, t = flat & 511;
        int sg = r0 + r;
        float v = acc[i];
        if (t == sg) {
            denom[b * S_ + sg] = 3.0f - v;
            v = 1.0f;
        }
        adj[base + (long)r * S_ + t] = v;
    }
}

// ---------------- aspect max-pool ----------------
__global__ void pool_kernel(const float* __restrict__ tok,
                            const int* __restrict__ am,
                            float* __restrict__ pool)
{
    int d = blockIdx.x * 256 + threadIdx.x;
    int b = blockIdx.y;
    if (d >= D_) return;
    const float* tp = tok + (long)b * S_ * D_;
    const int*   ap = am + b * S_;
    float m = -10000.0f;
    for (int s = 0; s < S_; s++) {
        float v = (ap[s] == 1) ? tp[(long)s * D_ + d] : -10000.0f;
        m = fmaxf(m, v);
    }
    pool[b * D_ + d] = m;
}

// ---------------- FFN2 + output assembly ----------------
__global__ void ffn2_kernel(const float* __restrict__ h,
                            const float* __restrict__ w2,
                            const float* __restrict__ b2,
                            const float* __restrict__ pool,
                            float* __restrict__ out)
{
    int bid = blockIdx.x;
    if (bid < 96) {
        int idx = bid * 256 + threadIdx.x;
        out[B_ * C_ + idx] = pool[idx];
    } else {
        int t = threadIdx.x;
        if (t < B_ * C_) {
            int b = t / C_, c = t % C_;
            const float* hp = h + b * D_;
            const float* wp = w2 + c * D_;
            float s = b2[c];
            for (int d = 0; d < D_; d++) s = fmaf(hp[d], wp[d], s);
            out[b * C_ + c] = s;
        }
    }
}

// ---------------- orchestration ----------------
extern "C" void kernel_launch(void* const* d_in, const int* in_sizes, int n_in,
                              void* d_out, int out_size)
{
    const float* x     = (const float*)d_in[0];
    const float* fmask = (const float*)d_in[1];
    const int*   amask = (const int*)  d_in[2];
    const float* wq    = (const float*)d_in[3];
    const float* wk    = (const float*)d_in[4];
    const float* gw    = (const float*)d_in[5];
    const float* gb    = (const float*)d_in[6];
    const float* w1    = (const float*)d_in[7];
    const float* b1    = (const float*)d_in[8];
    const float* w2    = (const float*)d_in[9];
    const float* b2    = (const float*)d_in[10];
    float* out = (float*)d_out;

    float *pqk, *pwqk, *padj, *pden, *pax, *pt1, *pt2, *ppool, *phid;
    cudaGetSymbolAddress((void**)&pqk,   g_qk);
    cudaGetSymbolAddress((void**)&pwqk,  g_wqk);
    cudaGetSymbolAddress((void**)&padj,  g_adj);
    cudaGetSymbolAddress((void**)&pden,  g_den);
    cudaGetSymbolAddress((void**)&pax,   g_ax);
    cudaGetSymbolAddress((void**)&pt1,   g_t1);
    cudaGetSymbolAddress((void**)&pt2,   g_t2);
    cudaGetSymbolAddress((void**)&ppool, g_pool);
    cudaGetSymbolAddress((void**)&phid,  g_hid);

    // 0) concat/transpose weights
    wqk_transpose<<<(H_*D_*DK_ + 255) / 256, 256>>>(wq, wk, pwqk);

    // 1) fused Q|K projection: [16384 x 768] @ [768 x 1536]
    gemm128<false,false,false,false><<<dim3(QKW/128, (B_*S_)/128, 1), 256>>>(
        x, pwqk, pqk, B_*S_, QKW, D_, 0L, 0L, 0L, 1, nullptr, nullptr, 0);

    // 2) fused scores -> softmax -> head-mean -> adjacency (+denom)
    {
        const int smem = (96*36 + 96*132 + 32*516 + 32 + 32 + 512) * 4;
        cudaFuncSetAttribute(adj_kernel,
                             cudaFuncAttributeMaxDynamicSharedMemorySize, smem);
        adj_kernel<<<dim3(16, B_), 256, smem>>>(pqk, fmask, padj, pden);
    }

    // 3) GCN layers
    {
        dim3 g(D_/128, S_/128, B_);   // (6, 4, 32)
        gemm128<false,false,false,false><<<g, 256>>>(
            padj, x, pax, S_, D_, S_,
            (long)S_*S_, (long)S_*D_, (long)S_*D_, 0, nullptr, nullptr, 0);
        gemm128<true,true,true,true><<<g, 256>>>(
            pax, gw, pt1, S_, D_, D_,
            (long)S_*D_, 0L, (long)S_*D_, 1, gb, pden, S_);
        gemm128<false,false,false,false><<<g, 256>>>(
            padj, pt1, pax, S_, D_, S_,
            (long)S_*S_, (long)S_*D_, (long)S_*D_, 0, nullptr, nullptr, 0);
        gemm128<true,true,true,true><<<g, 256>>>(
            pax, gw + (long)D_*D_, pt2, S_, D_, D_,
            (long)S_*D_, 0L, (long)S_*D_, 1, gb + D_, pden, S_);
    }

    // 4) aspect max-pool -> preds
    pool_kernel<<<dim3(3, B_), 256>>>(pt2, amask, ppool);

    // 5) FFN1: h = relu(preds @ W1^T + b1)
    sgemm_small<true,true,true><<<dim3(12, 1, 1), 256>>>(
        ppool, w1, phid, B_, D_, D_, b1);

    // 6) FFN2 + output: [preds_ (B*C) | preds (B*D)]
    ffn2_kernel<<<97, 256>>>(phid, w2, b2, ppool, out);
}

// round 4
// speedup vs baseline: 1.4131x; 1.1548x over previous
#include <cuda_runtime.h>
#include <math.h>
#include <stdint.h>

#define B_  32
#define S_  512
#define D_  768
#define H_  8
#define DK_ 96
#define C_  3
#define QKW 1536   // fused q|k width

// ---------------- scratch (device globals; no allocs allowed) ----------------
__device__ float g_qk  [(long)B_*S_*QKW];
__device__ float g_wqk [D_*QKW];
__device__ float g_adj [(long)B_*S_*S_];
__device__ float g_den [B_*S_];
__device__ float g_ax  [B_*S_*D_];
__device__ float g_t1  [B_*S_*D_];
__device__ float g_t2  [B_*S_*D_];
__device__ float g_pool[B_*D_];
__device__ float g_hid [B_*D_];

// ---------------- tf32 helpers ----------------
__device__ __forceinline__ void split1(float v, uint32_t& h, uint32_t& l) {
    uint32_t hb, lb;
    asm("cvt.rna.tf32.f32 %0, %1;" : "=r"(hb) : "f"(v));
    float lf = v - __uint_as_float(hb);
    asm("cvt.rna.tf32.f32 %0, %1;" : "=r"(lb) : "f"(lf));
    h = hb; l = lb;
}
__device__ __forceinline__ void split4(float4 v, uint4& h, uint4& l) {
    split1(v.x, h.x, l.x); split1(v.y, h.y, l.y);
    split1(v.z, h.z, l.z); split1(v.w, h.w, l.w);
}
__device__ __forceinline__ void mma_tf32(float* c, const uint32_t* a, const uint32_t* b) {
    asm volatile(
        "mma.sync.aligned.m16n8k8.row.col.f32.tf32.tf32.f32 "
        "{%0,%1,%2,%3}, {%4,%5,%6,%7}, {%8,%9}, {%0,%1,%2,%3};"
        : "+f"(c[0]), "+f"(c[1]), "+f"(c[2]), "+f"(c[3])
        : "r"(a[0]), "r"(a[1]), "r"(a[2]), "r"(a[3]), "r"(b[0]), "r"(b[1]));
}

// ---------------- fast exp (avoid MUFU bottleneck) ----------------
__device__ __forceinline__ float fast_exp(float x) {
    float y = fmaxf(x * 1.4426950408889634f, -126.0f);
    float t = __fadd_rn(y, 12582912.0f);
    float n = __fsub_rn(t, 12582912.0f);
    float f = __fsub_rn(y, n);
    float p = 0.0013333558f;
    p = fmaf(p, f, 0.0096181291f);
    p = fmaf(p, f, 0.0555041087f);
    p = fmaf(p, f, 0.2402265070f);
    p = fmaf(p, f, 0.6931471806f);
    p = fmaf(p, f, 1.0f);
    int e = (int)n;
    return __int_as_float(__float_as_int(p) + (e << 23));
}

// ---------------- weight concat/transpose ----------------
__global__ void wqk_transpose(const float* __restrict__ wq,
                              const float* __restrict__ wk,
                              float* __restrict__ out)
{
    int idx = blockIdx.x * 256 + threadIdx.x;
    if (idx >= H_ * D_ * DK_) return;
    int h = idx / (D_ * DK_);
    int r = idx % (D_ * DK_);
    int d = r / DK_, j = r % DK_;
    out[(long)d * QKW + h * DK_ + j]       = wq[idx];
    out[(long)d * QKW + D_ + h * DK_ + j]  = wk[idx];
}

// ================= tf32x3 GEMM via mma.sync (tensor pipe, no arch-suffix) ====
// C[M,N] = A[M,K] @ B.  Tile 128x128, warp tile 32x64, K-chunk 32, dbl-buffered.
// TRANSB: B global is [N,K]; else [K,N]. M%128==0, N%128==0, K%32==0.
#define KP 36                       // padded k-stride (floats): bank = (4g+t)&31
#define FSZ (128 * KP)              // one tile buffer (floats) = 4608
#define MMA_SMEM (8 * FSZ * 4)      // AH0,AH1,AL0,AL1,BH0,BH1,BL0,BL1 = 147456 B

template<bool TRANSB, bool BIAS, bool RELU, bool DENOM>
__global__ __launch_bounds__(256, 1) void gemm_mma(
    const float* __restrict__ A, const float* __restrict__ Bm, float* __restrict__ C,
    int M, int N, int K, long sA, long sB, long sC,
    const float* __restrict__ bias, const float* __restrict__ denom, int dstride)
{
    extern __shared__ float sm[];

    const int tid  = threadIdx.x;
    const int wid  = tid >> 5;
    const int lane = tid & 31;
    const int g    = lane >> 2;       // 0..7
    const int t    = lane & 3;        // 0..3
    const int wr   = wid & 3;         // warp row (4)
    const int wc   = wid >> 2;        // warp col (2)

    const int z = blockIdx.z;
    A  += (long)z * sA;
    Bm += (long)z * sB;
    C  += (long)z * sC;

    const int m0 = blockIdx.y * 128;
    const int n0 = blockIdx.x * 128;

    float acc[2][8][4];
#pragma unroll
    for (int i = 0; i < 2; i++)
#pragma unroll
        for (int j = 0; j < 8; j++)
#pragma unroll
            for (int e = 0; e < 4; e++) acc[i][j][e] = 0.0f;

    // staging: one k-chunk (32) of A and B into buffer s
    auto stage = [&](int c, int s) {
        {   // A: 128 rows x 32 k, row-major copy with split
            const int row = tid >> 1, kh = (tid & 1) * 16;
            const float* ap = A + (long)(m0 + row) * K + c * 32 + kh;
            float* dh = sm + s * FSZ + row * KP + kh;
            float* dl = sm + 2 * FSZ + s * FSZ + row * KP + kh;
#pragma unroll
            for (int i = 0; i < 4; i++) {
                float4 v = *(const float4*)(ap + i * 4);
                uint4 h, l; split4(v, h, l);
                *(uint4*)(dh + i * 4) = h;
                *(uint4*)(dl + i * 4) = l;
            }
        }
        if (TRANSB) {   // B[N,K]: rows are n, same copy pattern
            const int row = tid >> 1, kh = (tid & 1) * 16;
            const float* bp = Bm + (long)(n0 + row) * K + c * 32 + kh;
            float* dh = sm + 4 * FSZ + s * FSZ + row * KP + kh;
            float* dl = sm + 6 * FSZ + s * FSZ + row * KP + kh;
#pragma unroll
            for (int i = 0; i < 4; i++) {
                float4 v = *(const float4*)(bp + i * 4);
                uint4 h, l; split4(v, h, l);
                *(uint4*)(dh + i * 4) = h;
                *(uint4*)(dl + i * 4) = l;
            }
        } else {        // B[K,N]: transpose into [n][k]
            const int n  = tid & 127;
            const int kh = (tid >> 7) * 16;
            const float* bp = Bm + (long)(c * 32 + kh) * N + n0 + n;
            float* dh = sm + 4 * FSZ + s * FSZ + n * KP + kh;
            float* dl = sm + 6 * FSZ + s * FSZ + n * KP + kh;
#pragma unroll
            for (int i = 0; i < 4; i++) {
                float4 v;
                v.x = bp[(long)(4 * i + 0) * N];
                v.y = bp[(long)(4 * i + 1) * N];
                v.z = bp[(long)(4 * i + 2) * N];
                v.w = bp[(long)(4 * i + 3) * N];
                uint4 h, l; split4(v, h, l);
                *(uint4*)(dh + i * 4) = h;
                *(uint4*)(dl + i * 4) = l;
            }
        }
    };

    // mma over one staged k-chunk in buffer s
    auto compute = [&](int s) {
        const float* aH = sm + s * FSZ;
        const float* aL = sm + 2 * FSZ + s * FSZ;
        const float* bH = sm + 4 * FSZ + s * FSZ;
        const float* bL = sm + 6 * FSZ + s * FSZ;
#pragma unroll
        for (int kt = 0; kt < 4; kt++) {
            uint32_t ah[2][4], al[2][4];
#pragma unroll
            for (int mt = 0; mt < 2; mt++) {
                const int base = (wr * 32 + mt * 16 + g) * KP + kt * 8 + t;
                ah[mt][0] = __float_as_uint(aH[base]);
                ah[mt][1] = __float_as_uint(aH[base + 8 * KP]);
                ah[mt][2] = __float_as_uint(aH[base + 4]);
                ah[mt][3] = __float_as_uint(aH[base + 8 * KP + 4]);
                al[mt][0] = __float_as_uint(aL[base]);
                al[mt][1] = __float_as_uint(aL[base + 8 * KP]);
                al[mt][2] = __float_as_uint(aL[base + 4]);
                al[mt][3] = __float_as_uint(aL[base + 8 * KP + 4]);
            }
#pragma unroll
            for (int nt = 0; nt < 8; nt++) {
                const int nb = (wc * 64 + nt * 8 + g) * KP + kt * 8 + t;
                uint32_t bh[2], bl[2];
                bh[0] = __float_as_uint(bH[nb]);
                bh[1] = __float_as_uint(bH[nb + 4]);
                bl[0] = __float_as_uint(bL[nb]);
                bl[1] = __float_as_uint(bL[nb + 4]);
#pragma unroll
                for (int mt = 0; mt < 2; mt++) {
                    mma_tf32(acc[mt][nt], ah[mt], bh);
                    mma_tf32(acc[mt][nt], ah[mt], bl);
                    mma_tf32(acc[mt][nt], al[mt], bh);
                }
            }
        }
    };

    const int NC = K >> 5;
    stage(0, 0);
    __syncthreads();
    for (int it = 1; it < NC; it++) {
        compute((it - 1) & 1);
        stage(it, it & 1);
        __syncthreads();
    }
    compute((NC - 1) & 1);

    // ---- epilogue ----
#pragma unroll
    for (int mt = 0; mt < 2; mt++) {
        const int row0 = m0 + wr * 32 + mt * 16 + g;
        const int row1 = row0 + 8;
        float inv0 = 1.0f, inv1 = 1.0f;
        if (DENOM) {
            inv0 = 1.0f / denom[(long)z * dstride + row0];
            inv1 = 1.0f / denom[(long)z * dstride + row1];
        }
#pragma unroll
        for (int nt = 0; nt < 8; nt++) {
            const int col = n0 + wc * 64 + nt * 8 + 2 * t;
            float bv0 = 0.0f, bv1 = 0.0f;
            if (BIAS) { bv0 = bias[col]; bv1 = bias[col + 1]; }
            float v0 = acc[mt][nt][0] + bv0;
            float v1 = acc[mt][nt][1] + bv1;
            float v2 = acc[mt][nt][2] + bv0;
            float v3 = acc[mt][nt][3] + bv1;
            if (DENOM) { v0 *= inv0; v1 *= inv0; v2 *= inv1; v3 *= inv1; }
            if (RELU) {
                v0 = fmaxf(v0, 0.0f); v1 = fmaxf(v1, 0.0f);
                v2 = fmaxf(v2, 0.0f); v3 = fmaxf(v3, 0.0f);
            }
            *(float2*)&C[(long)row0 * N + col] = make_float2(v0, v1);
            *(float2*)&C[(long)row1 * N + col] = make_float2(v2, v3);
        }
    }
}

// ---------------- small guarded SGEMM (FFN1 only: M=32) ----------------------
template<bool TRANSB, bool BIAS, bool RELU>
__global__ __launch_bounds__(256) void sgemm_small(
    const float* __restrict__ A, const float* __restrict__ Bm, float* __restrict__ C,
    int M, int N, int K, const float* __restrict__ bias)
{
    __shared__ float As[16][68];
    __shared__ float Bs[16][68];
    const int m0 = blockIdx.y * 64, n0 = blockIdx.x * 64;
    const int tid = threadIdx.x;
    const int tx = tid & 15, ty = tid >> 4;
    float acc[4][4];
#pragma unroll
    for (int i = 0; i < 4; i++)
#pragma unroll
        for (int j = 0; j < 4; j++) acc[i][j] = 0.0f;
    const int arow = tid >> 2, akq = (tid & 3) * 4;
    for (int k0 = 0; k0 < K; k0 += 16) {
        float4 av = make_float4(0.f,0.f,0.f,0.f);
        if (m0 + arow < M)
            av = *(const float4*)&A[(long)(m0 + arow) * K + k0 + akq];
        As[akq+0][arow]=av.x; As[akq+1][arow]=av.y;
        As[akq+2][arow]=av.z; As[akq+3][arow]=av.w;
        if (!TRANSB) {
            const int kr = tid >> 4, nq = (tid & 15) * 4;
            float4 bv = make_float4(0.f,0.f,0.f,0.f);
            if (n0 + nq < N)
                bv = *(const float4*)&Bm[(long)(k0+kr)*N + n0 + nq];
            Bs[kr][nq+0]=bv.x; Bs[kr][nq+1]=bv.y; Bs[kr][nq+2]=bv.z; Bs[kr][nq+3]=bv.w;
        } else {
            const int nrow = tid >> 2, kq = (tid & 3) * 4;
            float4 bv = make_float4(0.f,0.f,0.f,0.f);
            if (n0 + nrow < N)
                bv = *(const float4*)&Bm[(long)(n0+nrow)*K + k0 + kq];
            Bs[kq+0][nrow]=bv.x; Bs[kq+1][nrow]=bv.y; Bs[kq+2][nrow]=bv.z; Bs[kq+3][nrow]=bv.w;
        }
        __syncthreads();
#pragma unroll
        for (int kk = 0; kk < 16; kk++) {
            float4 a = *(const float4*)&As[kk][ty*4];
            float4 b = *(const float4*)&Bs[kk][tx*4];
            acc[0][0]=fmaf(a.x,b.x,acc[0][0]); acc[0][1]=fmaf(a.x,b.y,acc[0][1]);
            acc[0][2]=fmaf(a.x,b.z,acc[0][2]); acc[0][3]=fmaf(a.x,b.w,acc[0][3]);
            acc[1][0]=fmaf(a.y,b.x,acc[1][0]); acc[1][1]=fmaf(a.y,b.y,acc[1][1]);
            acc[1][2]=fmaf(a.y,b.z,acc[1][2]); acc[1][3]=fmaf(a.y,b.w,acc[1][3]);
            acc[2][0]=fmaf(a.z,b.x,acc[2][0]); acc[2][1]=fmaf(a.z,b.y,acc[2][1]);
            acc[2][2]=fmaf(a.z,b.z,acc[2][2]); acc[2][3]=fmaf(a.z,b.w,acc[2][3]);
            acc[3][0]=fmaf(a.w,b.x,acc[3][0]); acc[3][1]=fmaf(a.w,b.y,acc[3][1]);
            acc[3][2]=fmaf(a.w,b.z,acc[3][2]); acc[3][3]=fmaf(a.w,b.w,acc[3][3]);
        }
        __syncthreads();
    }
#pragma unroll
    for (int i = 0; i < 4; i++) {
        int m = m0 + ty*4 + i;
        if (m >= M) continue;
#pragma unroll
        for (int j = 0; j < 4; j++) {
            int n = n0 + tx*4 + j;
            if (n < N) {
                float v = acc[i][j];
                if (BIAS) v += bias[n];
                if (RELU) v = fmaxf(v, 0.0f);
                C[(long)m * N + n] = v;
            }
        }
    }
}

// ---------------- fused scores->softmax->head-mean adjacency ----------------
__global__ __launch_bounds__(256) void adj_kernel(
    const float* __restrict__ qk, const float* __restrict__ fmask,
    float* __restrict__ adj, float* __restrict__ denom)
{
    extern __shared__ float smx[];
    float* sQT    = smx;                 // [96][36]
    float* sKT    = sQT + 96 * 36;       // [96][132]
    float* sS     = sKT + 96 * 132;      // [32][516]
    float* sScale = sS + 32 * 516;       // [32]
    float* sFr    = sScale + 32;         // [32]
    float* sFm    = sFr + 32;            // [512]

    const int b   = blockIdx.y;
    const int r0  = blockIdx.x * 32;
    const int tid = threadIdx.x;
    const int ty  = tid >> 5;
    const int tx  = tid & 31;

    if (tid < 32) sFr[tid] = fmask[b * S_ + r0 + tid];
    for (int i = tid; i < S_; i += 256) sFm[i] = fmask[b * S_ + i];

    float acc[64];
#pragma unroll
    for (int i = 0; i < 64; i++) acc[i] = 0.0f;

    const float rs = 0.10206207261596577f;   // 1/sqrt(96)
    const float* qb = qk + (long)(b * S_ + r0) * QKW;
    const float* kb = qk + (long)b * S_ * QKW + D_;

    for (int h = 0; h < H_; h++) {
        __syncthreads();
        for (int i = tid; i < 32 * 24; i += 256) {
            int r = i / 24, kq = (i % 24) * 4;
            float4 v = *(const float4*)&qb[(long)r * QKW + h * DK_ + kq];
            sQT[(kq+0)*36+r]=v.x; sQT[(kq+1)*36+r]=v.y;
            sQT[(kq+2)*36+r]=v.z; sQT[(kq+3)*36+r]=v.w;
        }
        for (int tc = 0; tc < 4; tc++) {
            __syncthreads();
            for (int i = tid; i < 128 * 24; i += 256) {
                int t = i / 24, kq = (i % 24) * 4;
                float4 v = *(const float4*)&kb[(long)(tc*128 + t) * QKW + h * DK_ + kq];
                sKT[(kq+0)*132+t]=v.x; sKT[(kq+1)*132+t]=v.y;
                sKT[(kq+2)*132+t]=v.z; sKT[(kq+3)*132+t]=v.w;
            }
            __syncthreads();
            float sa[4][4];
#pragma unroll
            for (int i = 0; i < 4; i++)
#pragma unroll
                for (int j = 0; j < 4; j++) sa[i][j] = 0.0f;
#pragma unroll 8
            for (int kk = 0; kk < 96; kk++) {
                float4 a  = *(const float4*)&sQT[kk * 36  + ty * 4];
                float4 bb = *(const float4*)&sKT[kk * 132 + tx * 4];
                sa[0][0]=fmaf(a.x,bb.x,sa[0][0]); sa[0][1]=fmaf(a.x,bb.y,sa[0][1]);
                sa[0][2]=fmaf(a.x,bb.z,sa[0][2]); sa[0][3]=fmaf(a.x,bb.w,sa[0][3]);
                sa[1][0]=fmaf(a.y,bb.x,sa[1][0]); sa[1][1]=fmaf(a.y,bb.y,sa[1][1]);
                sa[1][2]=fmaf(a.y,bb.z,sa[1][2]); sa[1][3]=fmaf(a.y,bb.w,sa[1][3]);
                sa[2][0]=fmaf(a.z,bb.x,sa[2][0]); sa[2][1]=fmaf(a.z,bb.y,sa[2][1]);
                sa[2][2]=fmaf(a.z,bb.z,sa[2][2]); sa[2][3]=fmaf(a.z,bb.w,sa[2][3]);
                sa[3][0]=fmaf(a.w,bb.x,sa[3][0]); sa[3][1]=fmaf(a.w,bb.y,sa[3][1]);
                sa[3][2]=fmaf(a.w,bb.z,sa[3][2]); sa[3][3]=fmaf(a.w,bb.w,sa[3][3]);
            }
#pragma unroll
            for (int i = 0; i < 4; i++) {
                int r = ty * 4 + i;
                float fr = sFr[r];
                float4 o;
                int t0 = tc * 128 + tx * 4;
#pragma unroll
                for (int j = 0; j < 4; j++) {
                    float v = sa[i][j] * rs;
                    if (fr * sFm[t0 + j] == 0.0f) v = -1e9f;
                    ((float*)&o)[j] = v;
                }
                *(float4*)&sS[r * 516 + t0] = o;
            }
        }
        __syncthreads();
        {
            int r = tid >> 3, lanei = tid & 7;
            float m = -INFINITY;
            for (int t = lanei; t < S_; t += 8) m = fmaxf(m, sS[r * 516 + t]);
            m = fmaxf(m, __shfl_xor_sync(0xffffffffu, m, 1));
            m = fmaxf(m, __shfl_xor_sync(0xffffffffu, m, 2));
            m = fmaxf(m, __shfl_xor_sync(0xffffffffu, m, 4));
            float s = 0.0f;
            for (int t = lanei; t < S_; t += 8) {
                float e = fast_exp(sS[r * 516 + t] - m);
                sS[r * 516 + t] = e;
                s += e;
            }
            s += __shfl_xor_sync(0xffffffffu, s, 1);
            s += __shfl_xor_sync(0xffffffffu, s, 2);
            s += __shfl_xor_sync(0xffffffffu, s, 4);
            if (lanei == 0) sScale[r] = 1.0f / (8.0f * s);
        }
        __syncthreads();
#pragma unroll
        for (int i = 0; i < 64; i++) {
            int flat = tid + 256 * i;
            int r = flat >> 9, t = flat & 511;
            acc[i] = fmaf(sS[r * 516 + t], sScale[r], acc[i]);
        }
    }

    long base = ((long)b * S_ + r0) * S_;
#pragma unroll
    for (int i = 0; i < 64; i++) {
        int flat = tid + 256 * i;
        int r = flat >> 9, t = flat & 511;
        int sg = r0 + r;
        float v = acc[i];
        if (t == sg) {
            denom[b * S_ + sg] = 3.0f - v;
            v = 1.0f;
        }
        adj[base + (long)r * S_ + t] = v;
    }
}

// ---------------- aspect max-pool ----------------
__global__ void pool_kernel(const float* __restrict__ tok,
                            const int* __restrict__ am,
                            float* __restrict__ pool)
{
    int d = blockIdx.x * 256 + threadIdx.x;
    int b = blockIdx.y;
    if (d >= D_) return;
    const float* tp = tok + (long)b * S_ * D_;
    const int*   ap = am + b * S_;
    float m = -10000.0f;
    for (int s = 0; s < S_; s++) {
        float v = (ap[s] == 1) ? tp[(long)s * D_ + d] : -10000.0f;
        m = fmaxf(m, v);
    }
    pool[b * D_ + d] = m;
}

// ---------------- FFN2 + output assembly ----------------
__global__ void ffn2_kernel(const float* __restrict__ h,
                            const float* __restrict__ w2,
                            const float* __restrict__ b2,
                            const float* __restrict__ pool,
                            float* __restrict__ out)
{
    int bid = blockIdx.x;
    if (bid < 96) {
        int idx = bid * 256 + threadIdx.x;
        out[B_ * C_ + idx] = pool[idx];
    } else {
        int t = threadIdx.x;
        if (t < B_ * C_) {
            int b = t / C_, c = t % C_;
            const float* hp = h + b * D_;
            const float* wp = w2 + c * D_;
            float s = b2[c];
            for (int d = 0; d < D_; d++) s = fmaf(hp[d], wp[d], s);
            out[b * C_ + c] = s;
        }
    }
}

// ---------------- orchestration ----------------
extern "C" void kernel_launch(void* const* d_in, const int* in_sizes, int n_in,
                              void* d_out, int out_size)
{
    const float* x     = (const float*)d_in[0];
    const float* fmask = (const float*)d_in[1];
    const int*   amask = (const int*)  d_in[2];
    const float* wq    = (const float*)d_in[3];
    const float* wk    = (const float*)d_in[4];
    const float* gw    = (const float*)d_in[5];
    const float* gb    = (const float*)d_in[6];
    const float* w1    = (const float*)d_in[7];
    const float* b1    = (const float*)d_in[8];
    const float* w2    = (const float*)d_in[9];
    const float* b2    = (const float*)d_in[10];
    float* out = (float*)d_out;

    float *pqk, *pwqk, *padj, *pden, *pax, *pt1, *pt2, *ppool, *phid;
    cudaGetSymbolAddress((void**)&pqk,   g_qk);
    cudaGetSymbolAddress((void**)&pwqk,  g_wqk);
    cudaGetSymbolAddress((void**)&padj,  g_adj);
    cudaGetSymbolAddress((void**)&pden,  g_den);
    cudaGetSymbolAddress((void**)&pax,   g_ax);
    cudaGetSymbolAddress((void**)&pt1,   g_t1);
    cudaGetSymbolAddress((void**)&pt2,   g_t2);
    cudaGetSymbolAddress((void**)&ppool, g_pool);
    cudaGetSymbolAddress((void**)&phid,  g_hid);

    cudaFuncSetAttribute(gemm_mma<false,false,false,false>,
                         cudaFuncAttributeMaxDynamicSharedMemorySize, MMA_SMEM);
    cudaFuncSetAttribute(gemm_mma<true,true,true,true>,
                         cudaFuncAttributeMaxDynamicSharedMemorySize, MMA_SMEM);

    // 0) concat/transpose weights
    wqk_transpose<<<(H_*D_*DK_ + 255) / 256, 256>>>(wq, wk, pwqk);

    // 1) fused Q|K projection: [16384 x 768] @ [768 x 1536]
    gemm_mma<false,false,false,false><<<dim3(QKW/128, (B_*S_)/128, 1), 256, MMA_SMEM>>>(
        x, pwqk, pqk, B_*S_, QKW, D_, 0L, 0L, 0L, nullptr, nullptr, 0);

    // 2) fused scores -> softmax -> head-mean -> adjacency (+denom)
    {
        const int smem = (96*36 + 96*132 + 32*516 + 32 + 32 + 512) * 4;
        cudaFuncSetAttribute(adj_kernel,
                             cudaFuncAttributeMaxDynamicSharedMemorySize, smem);
        adj_kernel<<<dim3(16, B_), 256, smem>>>(pqk, fmask, padj, pden);
    }

    // 3) GCN layers
    {
        dim3 g(D_/128, S_/128, B_);   // (6, 4, 32)
        gemm_mma<false,false,false,false><<<g, 256, MMA_SMEM>>>(
            padj, x, pax, S_, D_, S_,
            (long)S_*S_, (long)S_*D_, (long)S_*D_, nullptr, nullptr, 0);
        gemm_mma<true,true,true,true><<<g, 256, MMA_SMEM>>>(
            pax, gw, pt1, S_, D_, D_,
            (long)S_*D_, 0L, (long)S_*D_, gb, pden, S_);
        gemm_mma<false,false,false,false><<<g, 256, MMA_SMEM>>>(
            padj, pt1, pax, S_, D_, S_,
            (long)S_*S_, (long)S_*D_, (long)S_*D_, nullptr, nullptr, 0);
        gemm_mma<true,true,true,true><<<g, 256, MMA_SMEM>>>(
            pax, gw + (long)D_*D_, pt2, S_, D_, D_,
            (long)S_*D_, 0L, (long)S_*D_, gb + D_, pden, S_);
    }

    // 4) aspect max-pool -> preds
    pool_kernel<<<dim3(3, B_), 256>>>(pt2, amask, ppool);

    // 5) FFN1: h = relu(preds @ W1^T + b1)
    sgemm_small<true,true,true><<<dim3(12, 1, 1), 256>>>(
        ppool, w1, phid, B_, D_, D_, b1);

    // 6) FFN2 + output: [preds_ (B*C) | preds (B*D)]
    ffn2_kernel<<<97, 256>>>(phid, w2, b2, ppool, out);
}

// round 5
// speedup vs baseline: 1.5997x; 1.1321x over previous
#include <cuda_runtime.h>
#include <math.h>
#include <stdint.h>

#define B_  32
#define S_  512
#define D_  768
#define H_  8
#define DK_ 96
#define C_  3
#define QKW 1536   // fused q|k width

// ---------------- scratch (device globals; no allocs allowed) ----------------
__device__ float g_qk  [(long)B_*S_*QKW];
__device__ float g_wqk [D_*QKW];
__device__ float g_adj [(long)B_*S_*S_];
__device__ float g_den [B_*S_];
__device__ float g_ax  [B_*S_*D_];
__device__ float g_t1  [B_*S_*D_];
__device__ float g_t2  [B_*S_*D_];
__device__ float g_pool[B_*D_];
__device__ float g_hid [B_*D_];

// ---------------- tf32 helpers ----------------
__device__ __forceinline__ void split1(float v, uint32_t& h, uint32_t& l) {
    uint32_t hb, lb;
    asm("cvt.rna.tf32.f32 %0, %1;" : "=r"(hb) : "f"(v));
    float lf = v - __uint_as_float(hb);
    asm("cvt.rna.tf32.f32 %0, %1;" : "=r"(lb) : "f"(lf));
    h = hb; l = lb;
}
__device__ __forceinline__ void split4(float4 v, uint4& h, uint4& l) {
    split1(v.x, h.x, l.x); split1(v.y, h.y, l.y);
    split1(v.z, h.z, l.z); split1(v.w, h.w, l.w);
}
__device__ __forceinline__ void mma_tf32(float* c, const uint32_t* a, const uint32_t* b) {
    asm volatile(
        "mma.sync.aligned.m16n8k8.row.col.f32.tf32.tf32.f32 "
        "{%0,%1,%2,%3}, {%4,%5,%6,%7}, {%8,%9}, {%0,%1,%2,%3};"
        : "+f"(c[0]), "+f"(c[1]), "+f"(c[2]), "+f"(c[3])
        : "r"(a[0]), "r"(a[1]), "r"(a[2]), "r"(a[3]), "r"(b[0]), "r"(b[1]));
}

// ---------------- fast exp (avoid MUFU bottleneck) ----------------
__device__ __forceinline__ float fast_exp(float x) {
    float y = fmaxf(x * 1.4426950408889634f, -126.0f);
    float t = __fadd_rn(y, 12582912.0f);
    float n = __fsub_rn(t, 12582912.0f);
    float f = __fsub_rn(y, n);
    float p = 0.0013333558f;
    p = fmaf(p, f, 0.0096181291f);
    p = fmaf(p, f, 0.0555041087f);
    p = fmaf(p, f, 0.2402265070f);
    p = fmaf(p, f, 0.6931471806f);
    p = fmaf(p, f, 1.0f);
    int e = (int)n;
    return __int_as_float(__float_as_int(p) + (e << 23));
}

// ---------------- weight concat/transpose ----------------
__global__ void wqk_transpose(const float* __restrict__ wq,
                              const float* __restrict__ wk,
                              float* __restrict__ out)
{
    int idx = blockIdx.x * 256 + threadIdx.x;
    if (idx >= H_ * D_ * DK_) return;
    int h = idx / (D_ * DK_);
    int r = idx % (D_ * DK_);
    int d = r / DK_, j = r % DK_;
    out[(long)d * QKW + h * DK_ + j]       = wq[idx];
    out[(long)d * QKW + D_ + h * DK_ + j]  = wk[idx];
}

// ================= tf32x3 GEMM via mma.sync =================================
#define KP 36
#define FSZ (128 * KP)
#define MMA_SMEM (8 * FSZ * 4)

template<bool TRANSB, bool BIAS, bool RELU, bool DENOM>
__global__ __launch_bounds__(256, 1) void gemm_mma(
    const float* __restrict__ A, const float* __restrict__ Bm, float* __restrict__ C,
    int M, int N, int K, long sA, long sB, long sC,
    const float* __restrict__ bias, const float* __restrict__ denom, int dstride)
{
    extern __shared__ float sm[];

    const int tid  = threadIdx.x;
    const int wid  = tid >> 5;
    const int lane = tid & 31;
    const int g    = lane >> 2;
    const int t    = lane & 3;
    const int wr   = wid & 3;
    const int wc   = wid >> 2;

    const int z = blockIdx.z;
    A  += (long)z * sA;
    Bm += (long)z * sB;
    C  += (long)z * sC;

    const int m0 = blockIdx.y * 128;
    const int n0 = blockIdx.x * 128;

    float acc[2][8][4];
#pragma unroll
    for (int i = 0; i < 2; i++)
#pragma unroll
        for (int j = 0; j < 8; j++)
#pragma unroll
            for (int e = 0; e < 4; e++) acc[i][j][e] = 0.0f;

    float4 pa[4], pb[4];

    auto ldgf = [&](int c) {
        const int row = tid >> 1, kh = (tid & 1) * 16;
        const float* ap = A + (long)(m0 + row) * K + c * 32 + kh;
#pragma unroll
        for (int i = 0; i < 4; i++) pa[i] = *(const float4*)(ap + i * 4);
        if (TRANSB) {
            const float* bp = Bm + (long)(n0 + row) * K + c * 32 + kh;
#pragma unroll
            for (int i = 0; i < 4; i++) pb[i] = *(const float4*)(bp + i * 4);
        } else {
            const int n = tid & 127, kh2 = (tid >> 7) * 16;
            const float* bp = Bm + (long)(c * 32 + kh2) * N + n0 + n;
#pragma unroll
            for (int i = 0; i < 4; i++) {
                pb[i].x = bp[(long)(4 * i + 0) * N];
                pb[i].y = bp[(long)(4 * i + 1) * N];
                pb[i].z = bp[(long)(4 * i + 2) * N];
                pb[i].w = bp[(long)(4 * i + 3) * N];
            }
        }
    };
    auto stsf = [&](int s) {
        const int row = tid >> 1, kh = (tid & 1) * 16;
        float* dh = sm + s * FSZ + row * KP + kh;
        float* dl = sm + 2 * FSZ + s * FSZ + row * KP + kh;
#pragma unroll
        for (int i = 0; i < 4; i++) {
            uint4 h, l; split4(pa[i], h, l);
            *(uint4*)(dh + i * 4) = h;
            *(uint4*)(dl + i * 4) = l;
        }
        if (TRANSB) {
            float* bh_ = sm + 4 * FSZ + s * FSZ + row * KP + kh;
            float* bl_ = sm + 6 * FSZ + s * FSZ + row * KP + kh;
#pragma unroll
            for (int i = 0; i < 4; i++) {
                uint4 h, l; split4(pb[i], h, l);
                *(uint4*)(bh_ + i * 4) = h;
                *(uint4*)(bl_ + i * 4) = l;
            }
        } else {
            const int n = tid & 127, kh2 = (tid >> 7) * 16;
            float* bh_ = sm + 4 * FSZ + s * FSZ + n * KP + kh2;
            float* bl_ = sm + 6 * FSZ + s * FSZ + n * KP + kh2;
#pragma unroll
            for (int i = 0; i < 4; i++) {
                uint4 h, l; split4(pb[i], h, l);
                *(uint4*)(bh_ + i * 4) = h;
                *(uint4*)(bl_ + i * 4) = l;
            }
        }
    };

    auto compute = [&](int s) {
        const float* aH = sm + s * FSZ;
        const float* aL = sm + 2 * FSZ + s * FSZ;
        const float* bH = sm + 4 * FSZ + s * FSZ;
        const float* bL = sm + 6 * FSZ + s * FSZ;
#pragma unroll
        for (int kt = 0; kt < 4; kt++) {
            uint32_t ah[2][4], al[2][4];
#pragma unroll
            for (int mt = 0; mt < 2; mt++) {
                const int base = (wr * 32 + mt * 16 + g) * KP + kt * 8 + t;
                ah[mt][0] = __float_as_uint(aH[base]);
                ah[mt][1] = __float_as_uint(aH[base + 8 * KP]);
                ah[mt][2] = __float_as_uint(aH[base + 4]);
                ah[mt][3] = __float_as_uint(aH[base + 8 * KP + 4]);
                al[mt][0] = __float_as_uint(aL[base]);
                al[mt][1] = __float_as_uint(aL[base + 8 * KP]);
                al[mt][2] = __float_as_uint(aL[base + 4]);
                al[mt][3] = __float_as_uint(aL[base + 8 * KP + 4]);
            }
#pragma unroll
            for (int nt = 0; nt < 8; nt++) {
                const int nb = (wc * 64 + nt * 8 + g) * KP + kt * 8 + t;
                uint32_t bh[2], bl[2];
                bh[0] = __float_as_uint(bH[nb]);
                bh[1] = __float_as_uint(bH[nb + 4]);
                bl[0] = __float_as_uint(bL[nb]);
                bl[1] = __float_as_uint(bL[nb + 4]);
#pragma unroll
                for (int mt = 0; mt < 2; mt++) {
                    mma_tf32(acc[mt][nt], ah[mt], bh);
                    mma_tf32(acc[mt][nt], ah[mt], bl);
                    mma_tf32(acc[mt][nt], al[mt], bh);
                }
            }
        }
    };

    const int NC = K >> 5;
    ldgf(0); stsf(0);
    __syncthreads();
    for (int it = 1; it < NC; it++) {
        ldgf(it);                 // prefetch next chunk (latency hidden under mma)
        compute((it - 1) & 1);
        stsf(it & 1);
        __syncthreads();
    }
    compute((NC - 1) & 1);

    // ---- epilogue ----
#pragma unroll
    for (int mt = 0; mt < 2; mt++) {
        const int row0 = m0 + wr * 32 + mt * 16 + g;
        const int row1 = row0 + 8;
        float inv0 = 1.0f, inv1 = 1.0f;
        if (DENOM) {
            inv0 = 1.0f / denom[(long)z * dstride + row0];
            inv1 = 1.0f / denom[(long)z * dstride + row1];
        }
#pragma unroll
        for (int nt = 0; nt < 8; nt++) {
            const int col = n0 + wc * 64 + nt * 8 + 2 * t;
            float bv0 = 0.0f, bv1 = 0.0f;
            if (BIAS) { bv0 = bias[col]; bv1 = bias[col + 1]; }
            float v0 = acc[mt][nt][0] + bv0;
            float v1 = acc[mt][nt][1] + bv1;
            float v2 = acc[mt][nt][2] + bv0;
            float v3 = acc[mt][nt][3] + bv1;
            if (DENOM) { v0 *= inv0; v1 *= inv0; v2 *= inv1; v3 *= inv1; }
            if (RELU) {
                v0 = fmaxf(v0, 0.0f); v1 = fmaxf(v1, 0.0f);
                v2 = fmaxf(v2, 0.0f); v3 = fmaxf(v3, 0.0f);
            }
            *(float2*)&C[(long)row0 * N + col] = make_float2(v0, v1);
            *(float2*)&C[(long)row1 * N + col] = make_float2(v2, v3);
        }
    }
}

// ---------------- small guarded SGEMM (FFN1 only: M=32) ----------------------
template<bool TRANSB, bool BIAS, bool RELU>
__global__ __launch_bounds__(256) void sgemm_small(
    const float* __restrict__ A, const float* __restrict__ Bm, float* __restrict__ C,
    int M, int N, int K, const float* __restrict__ bias)
{
    __shared__ float As[16][68];
    __shared__ float Bs[16][68];
    const int m0 = blockIdx.y * 64, n0 = blockIdx.x * 64;
    const int tid = threadIdx.x;
    const int tx = tid & 15, ty = tid >> 4;
    float acc[4][4];
#pragma unroll
    for (int i = 0; i < 4; i++)
#pragma unroll
        for (int j = 0; j < 4; j++) acc[i][j] = 0.0f;
    const int arow = tid >> 2, akq = (tid & 3) * 4;
    for (int k0 = 0; k0 < K; k0 += 16) {
        float4 av = make_float4(0.f,0.f,0.f,0.f);
        if (m0 + arow < M)
            av = *(const float4*)&A[(long)(m0 + arow) * K + k0 + akq];
        As[akq+0][arow]=av.x; As[akq+1][arow]=av.y;
        As[akq+2][arow]=av.z; As[akq+3][arow]=av.w;
        if (!TRANSB) {
            const int kr = tid >> 4, nq = (tid & 15) * 4;
            float4 bv = make_float4(0.f,0.f,0.f,0.f);
            if (n0 + nq < N)
                bv = *(const float4*)&Bm[(long)(k0+kr)*N + n0 + nq];
            Bs[kr][nq+0]=bv.x; Bs[kr][nq+1]=bv.y; Bs[kr][nq+2]=bv.z; Bs[kr][nq+3]=bv.w;
        } else {
            const int nrow = tid >> 2, kq = (tid & 3) * 4;
            float4 bv = make_float4(0.f,0.f,0.f,0.f);
            if (n0 + nrow < N)
                bv = *(const float4*)&Bm[(long)(n0+nrow)*K + k0 + kq];
            Bs[kq+0][nrow]=bv.x; Bs[kq+1][nrow]=bv.y; Bs[kq+2][nrow]=bv.z; Bs[kq+3][nrow]=bv.w;
        }
        __syncthreads();
#pragma unroll
        for (int kk = 0; kk < 16; kk++) {
            float4 a = *(const float4*)&As[kk][ty*4];
            float4 b = *(const float4*)&Bs[kk][tx*4];
            acc[0][0]=fmaf(a.x,b.x,acc[0][0]); acc[0][1]=fmaf(a.x,b.y,acc[0][1]);
            acc[0][2]=fmaf(a.x,b.z,acc[0][2]); acc[0][3]=fmaf(a.x,b.w,acc[0][3]);
            acc[1][0]=fmaf(a.y,b.x,acc[1][0]); acc[1][1]=fmaf(a.y,b.y,acc[1][1]);
            acc[1][2]=fmaf(a.y,b.z,acc[1][2]); acc[1][3]=fmaf(a.y,b.w,acc[1][3]);
            acc[2][0]=fmaf(a.z,b.x,acc[2][0]); acc[2][1]=fmaf(a.z,b.y,acc[2][1]);
            acc[2][2]=fmaf(a.z,b.z,acc[2][2]); acc[2][3]=fmaf(a.z,b.w,acc[2][3]);
            acc[3][0]=fmaf(a.w,b.x,acc[3][0]); acc[3][1]=fmaf(a.w,b.y,acc[3][1]);
            acc[3][2]=fmaf(a.w,b.z,acc[3][2]); acc[3][3]=fmaf(a.w,b.w,acc[3][3]);
        }
        __syncthreads();
    }
#pragma unroll
    for (int i = 0; i < 4; i++) {
        int m = m0 + ty*4 + i;
        if (m >= M) continue;
#pragma unroll
        for (int j = 0; j < 4; j++) {
            int n = n0 + tx*4 + j;
            if (n < N) {
                float v = acc[i][j];
                if (BIAS) v += bias[n];
                if (RELU) v = fmaxf(v, 0.0f);
                C[(long)m * N + n] = v;
            }
        }
    }
}

// ============== fused scores(mma tf32x3)->softmax->head-mean adjacency ======
// Block = (b, 32-row tile). 8 warps; warp w owns S-cols [w*64, w*64+64).
// K is staged warp-locally in k-slices of 8 (kp=12) -> no block syncs in k loop.
__global__ __launch_bounds__(256, 1) void adj_kernel(
    const float* __restrict__ qk, const float* __restrict__ fmask,
    float* __restrict__ adj, float* __restrict__ denom)
{
    extern __shared__ float smx[];
    float* sQh = smx;                    // [32][100]
    float* sQl = sQh + 3200;
    float* sKh = sQl + 3200;             // [512][12]
    float* sKl = sKh + 6144;
    float* sS  = sKl + 6144;             // [32][516]
    float* sScale = sS + 32 * 516;
    float* sFr = sScale + 32;
    float* sFm = sFr + 32;               // [512]

    const int b   = blockIdx.y;
    const int r0  = blockIdx.x * 32;
    const int tid = threadIdx.x;
    const int wid = tid >> 5;
    const int lane = tid & 31;
    const int g   = lane >> 2;
    const int qt  = lane & 3;

    if (tid < 32) sFr[tid] = fmask[b * S_ + r0 + tid];
    for (int i = tid; i < S_; i += 256) sFm[i] = fmask[b * S_ + i];

    float macc[64];
#pragma unroll
    for (int i = 0; i < 64; i++) macc[i] = 0.0f;

    const float rs = 0.10206207261596577f;   // 1/sqrt(96)
    const float* qb = qk + ((long)b * S_ + r0) * QKW;
    const float* kb = qk + (long)b * S_ * QKW + D_;

    float4 pk[4];
    auto ldgK = [&](int h, int ks) {
        const float* src = kb + (long)(tid * 2) * QKW + h * DK_ + ks * 8;
        pk[0] = *(const float4*)(src);
        pk[1] = *(const float4*)(src + 4);
        pk[2] = *(const float4*)(src + QKW);
        pk[3] = *(const float4*)(src + QKW + 4);
    };
    auto stsK = [&]() {   // warp-local: thread rows tid*2, tid*2+1 (within warp stripe)
        float* dh = sKh + (tid * 2) * 12;
        float* dl = sKl + (tid * 2) * 12;
        uint4 h0, l0, h1, l1;
        split4(pk[0], h0, l0); split4(pk[1], h1, l1);
        *(uint4*)(dh)     = h0; *(uint4*)(dh + 4)  = h1;
        *(uint4*)(dl)     = l0; *(uint4*)(dl + 4)  = l1;
        split4(pk[2], h0, l0); split4(pk[3], h1, l1);
        *(uint4*)(dh + 12) = h0; *(uint4*)(dh + 16) = h1;
        *(uint4*)(dl + 12) = l0; *(uint4*)(dl + 16) = l1;
    };

    ldgK(0, 0);

    for (int h = 0; h < H_; h++) {
        // ---- stage Q (block-shared; protected by head-top sync below) ----
#pragma unroll
        for (int j = 0; j < 3; j++) {
            int f = tid + 256 * j;
            int row = f / 24, c4 = (f % 24) * 4;
            float4 v = *(const float4*)&qb[(long)row * QKW + h * DK_ + c4];
            uint4 hh, ll; split4(v, hh, ll);
            *(uint4*)&sQh[row * 100 + c4] = hh;
            *(uint4*)&sQl[row * 100 + c4] = ll;
        }
        __syncthreads();   // Q visible to all warps; also fences prior-head sS reads

        float sacc[2][8][4];
#pragma unroll
        for (int i = 0; i < 2; i++)
#pragma unroll
            for (int j = 0; j < 8; j++)
#pragma unroll
                for (int e = 0; e < 4; e++) sacc[i][j][e] = 0.0f;

        for (int ks = 0; ks < 12; ks++) {
            stsK();
            if (ks < 11)      ldgK(h, ks + 1);
            else if (h < 7)   ldgK(h + 1, 0);
            __syncwarp();
            // compute slice ks
#pragma unroll 1
            {
                uint32_t ah[2][4], al[2][4];
#pragma unroll
                for (int mt = 0; mt < 2; mt++) {
                    const int ab = (mt * 16 + g) * 100 + ks * 8 + qt;
                    ah[mt][0] = __float_as_uint(sQh[ab]);
                    ah[mt][1] = __float_as_uint(sQh[ab + 800]);
                    ah[mt][2] = __float_as_uint(sQh[ab + 4]);
                    ah[mt][3] = __float_as_uint(sQh[ab + 804]);
                    al[mt][0] = __float_as_uint(sQl[ab]);
                    al[mt][1] = __float_as_uint(sQl[ab + 800]);
                    al[mt][2] = __float_as_uint(sQl[ab + 4]);
                    al[mt][3] = __float_as_uint(sQl[ab + 804]);
                }
#pragma unroll
                for (int nt = 0; nt < 8; nt++) {
                    const int nb = (wid * 64 + nt * 8 + g) * 12 + qt;
                    uint32_t bh[2], bl[2];
                    bh[0] = __float_as_uint(sKh[nb]);
                    bh[1] = __float_as_uint(sKh[nb + 4]);
                    bl[0] = __float_as_uint(sKl[nb]);
                    bl[1] = __float_as_uint(sKl[nb + 4]);
#pragma unroll
                    for (int mt = 0; mt < 2; mt++) {
                        mma_tf32(sacc[mt][nt], ah[mt], bh);
                        mma_tf32(sacc[mt][nt], ah[mt], bl);
                        mma_tf32(sacc[mt][nt], al[mt], bh);
                    }
                }
            }
            __syncwarp();  // before next stsK overwrites warp-local K buffer
        }

        // ---- write masked/scaled scores to sS ----
#pragma unroll
        for (int mt = 0; mt < 2; mt++) {
            const int r1 = mt * 16 + g, r2 = r1 + 8;
            const float f1 = sFr[r1], f2 = sFr[r2];
#pragma unroll
            for (int nt = 0; nt < 8; nt++) {
                const int col = wid * 64 + nt * 8 + 2 * qt;
                const float m0v = sFm[col], m1v = sFm[col + 1];
                float v0 = sacc[mt][nt][0] * rs; if (f1 * m0v == 0.0f) v0 = -1e9f;
                float v1 = sacc[mt][nt][1] * rs; if (f1 * m1v == 0.0f) v1 = -1e9f;
                float v2 = sacc[mt][nt][2] * rs; if (f2 * m0v == 0.0f) v2 = -1e9f;
                float v3 = sacc[mt][nt][3] * rs; if (f2 * m1v == 0.0f) v3 = -1e9f;
                *(float2*)&sS[r1 * 516 + col] = make_float2(v0, v1);
                *(float2*)&sS[r2 * 516 + col] = make_float2(v2, v3);
            }
        }
        __syncthreads();

        // ---- softmax: 8 threads per row ----
        {
            int r = tid >> 3, li = tid & 7;
            float m = -INFINITY;
            for (int t2 = li; t2 < S_; t2 += 8) m = fmaxf(m, sS[r * 516 + t2]);
            m = fmaxf(m, __shfl_xor_sync(0xffffffffu, m, 1));
            m = fmaxf(m, __shfl_xor_sync(0xffffffffu, m, 2));
            m = fmaxf(m, __shfl_xor_sync(0xffffffffu, m, 4));
            float s = 0.0f;
            for (int t2 = li; t2 < S_; t2 += 8) {
                float e = fast_exp(sS[r * 516 + t2] - m);
                sS[r * 516 + t2] = e;
                s += e;
            }
            s += __shfl_xor_sync(0xffffffffu, s, 1);
            s += __shfl_xor_sync(0xffffffffu, s, 2);
            s += __shfl_xor_sync(0xffffffffu, s, 4);
            if (li == 0) sScale[r] = 1.0f / (8.0f * s);
        }
        __syncthreads();

        // ---- accumulate head-mean ----
#pragma unroll
        for (int i = 0; i < 64; i++) {
            int flat = tid + 256 * i;
            int r = flat >> 9, t2 = flat & 511;
            macc[i] = fmaf(sS[r * 516 + t2], sScale[r], macc[i]);
        }
        __syncthreads();
    }

    long base = ((long)b * S_ + r0) * S_;
#pragma unroll
    for (int i = 0; i < 64; i++) {
        int flat = tid + 256 * i;
        int r = flat >> 9, t2 = flat & 511;
        int sg = r0 + r;
        float v = macc[i];
        if (t2 == sg) {
            denom[b * S_ + sg] = 3.0f - v;
            v = 1.0f;
        }
        adj[base + (long)r * S_ + t2] = v;
    }
}

// ---------------- aspect max-pool ----------------
__global__ void pool_kernel(const float* __restrict__ tok,
                            const int* __restrict__ am,
                            float* __restrict__ pool)
{
    int d = blockIdx.x * 256 + threadIdx.x;
    int b = blockIdx.y;
    if (d >= D_) return;
    const float* tp = tok + (long)b * S_ * D_;
    const int*   ap = am + b * S_;
    float m = -10000.0f;
    for (int s = 0; s < S_; s++) {
        float v = (ap[s] == 1) ? tp[(long)s * D_ + d] : -10000.0f;
        m = fmaxf(m, v);
    }
    pool[b * D_ + d] = m;
}

// ---------------- FFN2 + output assembly ----------------
__global__ void ffn2_kernel(const float* __restrict__ h,
                            const float* __restrict__ w2,
                            const float* __restrict__ b2,
                            const float* __restrict__ pool,
                            float* __restrict__ out)
{
    int bid = blockIdx.x;
    if (bid < 96) {
        int idx = bid * 256 + threadIdx.x;
        out[B_ * C_ + idx] = pool[idx];
    } else {
        int t = threadIdx.x;
        if (t < B_ * C_) {
            int b = t / C_, c = t % C_;
            const float* hp = h + b * D_;
            const float* wp = w2 + c * D_;
            float s = b2[c];
            for (int d = 0; d < D_; d++) s = fmaf(hp[d], wp[d], s);
            out[b * C_ + c] = s;
        }
    }
}

// ---------------- orchestration ----------------
extern "C" void kernel_launch(void* const* d_in, const int* in_sizes, int n_in,
                              void* d_out, int out_size)
{
    const float* x     = (const float*)d_in[0];
    const float* fmask = (const float*)d_in[1];
    const int*   amask = (const int*)  d_in[2];
    const float* wq    = (const float*)d_in[3];
    const float* wk    = (const float*)d_in[4];
    const float* gw    = (const float*)d_in[5];
    const float* gb    = (const float*)d_in[6];
    const float* w1    = (const float*)d_in[7];
    const float* b1    = (const float*)d_in[8];
    const float* w2    = (const float*)d_in[9];
    const float* b2    = (const float*)d_in[10];
    float* out = (float*)d_out;

    float *pqk, *pwqk, *padj, *pden, *pax, *pt1, *pt2, *ppool, *phid;
    cudaGetSymbolAddress((void**)&pqk,   g_qk);
    cudaGetSymbolAddress((void**)&pwqk,  g_wqk);
    cudaGetSymbolAddress((void**)&padj,  g_adj);
    cudaGetSymbolAddress((void**)&pden,  g_den);
    cudaGetSymbolAddress((void**)&pax,   g_ax);
    cudaGetSymbolAddress((void**)&pt1,   g_t1);
    cudaGetSymbolAddress((void**)&pt2,   g_t2);
    cudaGetSymbolAddress((void**)&ppool, g_pool);
    cudaGetSymbolAddress((void**)&phid,  g_hid);

    cudaFuncSetAttribute(gemm_mma<false,false,false,false>,
                         cudaFuncAttributeMaxDynamicSharedMemorySize, MMA_SMEM);
    cudaFuncSetAttribute(gemm_mma<true,true,true,true>,
                         cudaFuncAttributeMaxDynamicSharedMemorySize, MMA_SMEM);

    // 0) concat/transpose weights
    wqk_transpose<<<(H_*D_*DK_ + 255) / 256, 256>>>(wq, wk, pwqk);

    // 1) fused Q|K projection
    gemm_mma<false,false,false,false><<<dim3(QKW/128, (B_*S_)/128, 1), 256, MMA_SMEM>>>(
        x, pwqk, pqk, B_*S_, QKW, D_, 0L, 0L, 0L, nullptr, nullptr, 0);

    // 2) fused scores(mma) -> softmax -> head-mean -> adjacency (+denom)
    {
        const int smem = (3200*2 + 6144*2 + 32*516 + 32 + 32 + 512) * 4; // 143104
        cudaFuncSetAttribute(adj_kernel,
                             cudaFuncAttributeMaxDynamicSharedMemorySize, smem);
        adj_kernel<<<dim3(16, B_), 256, smem>>>(pqk, fmask, padj, pden);
    }

    // 3) GCN layers
    {
        dim3 g(D_/128, S_/128, B_);   // (6, 4, 32)
        gemm_mma<false,false,false,false><<<g, 256, MMA_SMEM>>>(
            padj, x, pax, S_, D_, S_,
            (long)S_*S_, (long)S_*D_, (long)S_*D_, nullptr, nullptr, 0);
        gemm_mma<true,true,true,true><<<g, 256, MMA_SMEM>>>(
            pax, gw, pt1, S_, D_, D_,
            (long)S_*D_, 0L, (long)S_*D_, gb, pden, S_);
        gemm_mma<false,false,false,false><<<g, 256, MMA_SMEM>>>(
            padj, pt1, pax, S_, D_, S_,
            (long)S_*S_, (long)S_*D_, (long)S_*D_, nullptr, nullptr, 0);
        gemm_mma<true,true,true,true><<<g, 256, MMA_SMEM>>>(
            pax, gw + (long)D_*D_, pt2, S_, D_, D_,
            (long)S_*D_, 0L, (long)S_*D_, gb + D_, pden, S_);
    }

    // 4) aspect max-pool -> preds
    pool_kernel<<<dim3(3, B_), 256>>>(pt2, amask, ppool);

    // 5) FFN1
    sgemm_small<true,true,true><<<dim3(12, 1, 1), 256>>>(
        ppool, w1, phid, B_, D_, D_, b1);

    // 6) FFN2 + output
    ffn2_kernel<<<97, 256>>>(phid, w2, b2, ppool, out);
}

// round 6
// speedup vs baseline: 1.6889x; 1.0557x over previous
#include <cuda_runtime.h>
#include <math.h>
#include <stdint.h>

#define B_  32
#define S_  512
#define D_  768
#define H_  8
#define DK_ 96
#define C_  3
#define QKW 1536   // fused q|k width

// ---------------- scratch (device globals; no allocs allowed) ----------------
__device__ float g_qk  [(long)B_*S_*QKW];
__device__ float g_wqk [D_*QKW];
__device__ float g_adj [(long)B_*S_*S_];
__device__ float g_den [B_*S_];
__device__ float g_ax  [B_*S_*D_];
__device__ float g_t1  [B_*S_*D_];
__device__ float g_t2  [B_*S_*D_];
__device__ float g_pool[B_*D_];
__device__ float g_hid [B_*D_];

// ---------------- tf32 helpers ----------------
__device__ __forceinline__ void split1(float v, uint32_t& h, uint32_t& l) {
    uint32_t hb, lb;
    asm("cvt.rna.tf32.f32 %0, %1;" : "=r"(hb) : "f"(v));
    float lf = v - __uint_as_float(hb);
    asm("cvt.rna.tf32.f32 %0, %1;" : "=r"(lb) : "f"(lf));
    h = hb; l = lb;
}
__device__ __forceinline__ void split4(float4 v, uint4& h, uint4& l) {
    split1(v.x, h.x, l.x); split1(v.y, h.y, l.y);
    split1(v.z, h.z, l.z); split1(v.w, h.w, l.w);
}
__device__ __forceinline__ void mma_tf32(float* c, const uint32_t* a, const uint32_t* b) {
    asm volatile(
        "mma.sync.aligned.m16n8k8.row.col.f32.tf32.tf32.f32 "
        "{%0,%1,%2,%3}, {%4,%5,%6,%7}, {%8,%9}, {%0,%1,%2,%3};"
        : "+f"(c[0]), "+f"(c[1]), "+f"(c[2]), "+f"(c[3])
        : "r"(a[0]), "r"(a[1]), "r"(a[2]), "r"(a[3]), "r"(b[0]), "r"(b[1]));
}

// ---------------- fast exp ----------------
__device__ __forceinline__ float fast_exp(float x) {
    float y = fmaxf(x * 1.4426950408889634f, -126.0f);
    float t = __fadd_rn(y, 12582912.0f);
    float n = __fsub_rn(t, 12582912.0f);
    float f = __fsub_rn(y, n);
    float p = 0.0013333558f;
    p = fmaf(p, f, 0.0096181291f);
    p = fmaf(p, f, 0.0555041087f);
    p = fmaf(p, f, 0.2402265070f);
    p = fmaf(p, f, 0.6931471806f);
    p = fmaf(p, f, 1.0f);
    int e = (int)n;
    return __int_as_float(__float_as_int(p) + (e << 23));
}

// ---------------- weight concat/transpose ----------------
__global__ void wqk_transpose(const float* __restrict__ wq,
                              const float* __restrict__ wk,
                              float* __restrict__ out)
{
    int idx = blockIdx.x * 256 + threadIdx.x;
    if (idx >= H_ * D_ * DK_) return;
    int h = idx / (D_ * DK_);
    int r = idx % (D_ * DK_);
    int d = r / DK_, j = r % DK_;
    out[(long)d * QKW + h * DK_ + j]       = wq[idx];
    out[(long)d * QKW + D_ + h * DK_ + j]  = wk[idx];
}

// ================= tf32x3 GEMM: 128x128 tile, 4 warps of 64x64, KC=16 =======
// 2 CTAs/SM (82KB smem). TRANSB: B is [N,K]; else [K,N]. M,N %128==0, K%16==0.
#define KP2 20
#define GSZ (128 * KP2)                 // 2560 floats per buffer
#define MMA_SMEM (8 * GSZ * 4)          // 81920 B

template<bool TRANSB, bool BIAS, bool RELU, bool DENOM>
__global__ __launch_bounds__(128, 2) void gemm_mma(
    const float* __restrict__ A, const float* __restrict__ Bm, float* __restrict__ C,
    int M, int N, int K, long sA, long sB, long sC,
    const float* __restrict__ bias, const float* __restrict__ denom, int dstride)
{
    extern __shared__ float sm[];

    const int tid  = threadIdx.x;
    const int wid  = tid >> 5;
    const int lane = tid & 31;
    const int g    = lane >> 2;
    const int t    = lane & 3;
    const int wr   = wid & 1;         // warp row (2) -> 64 rows
    const int wc   = wid >> 1;        // warp col (2) -> 64 cols

    const int z = blockIdx.z;
    A  += (long)z * sA;
    Bm += (long)z * sB;
    C  += (long)z * sC;

    const int m0 = blockIdx.y * 128;
    const int n0 = blockIdx.x * 128;

    float acc[4][8][4];
#pragma unroll
    for (int i = 0; i < 4; i++)
#pragma unroll
        for (int j = 0; j < 8; j++)
#pragma unroll
            for (int e = 0; e < 4; e++) acc[i][j][e] = 0.0f;

    float4 pa[4], pb[4];

    auto ldgf = [&](int c) {
        const float* ap = A + (long)(m0 + tid) * K + c * 16;
#pragma unroll
        for (int i = 0; i < 4; i++) pa[i] = *(const float4*)(ap + i * 4);
        if (TRANSB) {
            const float* bp = Bm + (long)(n0 + tid) * K + c * 16;
#pragma unroll
            for (int i = 0; i < 4; i++) pb[i] = *(const float4*)(bp + i * 4);
        } else {
            const float* bp = Bm + (long)(c * 16) * N + n0 + tid;
#pragma unroll
            for (int i = 0; i < 4; i++) {
                pb[i].x = bp[(long)(4 * i + 0) * N];
                pb[i].y = bp[(long)(4 * i + 1) * N];
                pb[i].z = bp[(long)(4 * i + 2) * N];
                pb[i].w = bp[(long)(4 * i + 3) * N];
            }
        }
    };
    auto stsf = [&](int s) {
        float* dah = sm + s * GSZ + tid * KP2;
        float* dal = sm + (2 + s) * GSZ + tid * KP2;
        float* dbh = sm + (4 + s) * GSZ + tid * KP2;
        float* dbl = sm + (6 + s) * GSZ + tid * KP2;
#pragma unroll
        for (int i = 0; i < 4; i++) {
            uint4 h, l; split4(pa[i], h, l);
            *(uint4*)(dah + i * 4) = h;
            *(uint4*)(dal + i * 4) = l;
        }
#pragma unroll
        for (int i = 0; i < 4; i++) {
            uint4 h, l; split4(pb[i], h, l);
            *(uint4*)(dbh + i * 4) = h;
            *(uint4*)(dbl + i * 4) = l;
        }
    };

    auto compute = [&](int s) {
        const float* aH = sm + s * GSZ;
        const float* aL = sm + (2 + s) * GSZ;
        const float* bH = sm + (4 + s) * GSZ;
        const float* bL = sm + (6 + s) * GSZ;
#pragma unroll
        for (int kt = 0; kt < 2; kt++) {
            uint32_t ah[4][4], al[4][4];
#pragma unroll
            for (int mt = 0; mt < 4; mt++) {
                const int base = (wr * 64 + mt * 16 + g) * KP2 + kt * 8 + t;
                ah[mt][0] = __float_as_uint(aH[base]);
                ah[mt][1] = __float_as_uint(aH[base + 8 * KP2]);
                ah[mt][2] = __float_as_uint(aH[base + 4]);
                ah[mt][3] = __float_as_uint(aH[base + 8 * KP2 + 4]);
                al[mt][0] = __float_as_uint(aL[base]);
                al[mt][1] = __float_as_uint(aL[base + 8 * KP2]);
                al[mt][2] = __float_as_uint(aL[base + 4]);
                al[mt][3] = __float_as_uint(aL[base + 8 * KP2 + 4]);
            }
#pragma unroll
            for (int nt = 0; nt < 8; nt++) {
                const int nb = (wc * 64 + nt * 8 + g) * KP2 + kt * 8 + t;
                uint32_t bh[2], bl[2];
                bh[0] = __float_as_uint(bH[nb]);
                bh[1] = __float_as_uint(bH[nb + 4]);
                bl[0] = __float_as_uint(bL[nb]);
                bl[1] = __float_as_uint(bL[nb + 4]);
#pragma unroll
                for (int mt = 0; mt < 4; mt++) {
                    mma_tf32(acc[mt][nt], ah[mt], bh);
                    mma_tf32(acc[mt][nt], ah[mt], bl);
                    mma_tf32(acc[mt][nt], al[mt], bh);
                }
            }
        }
    };

    const int NC = K >> 4;
    ldgf(0); stsf(0);
    __syncthreads();
    for (int it = 1; it < NC; it++) {
        ldgf(it);
        compute((it - 1) & 1);
        stsf(it & 1);
        __syncthreads();
    }
    compute((NC - 1) & 1);

    // ---- epilogue ----
#pragma unroll
    for (int mt = 0; mt < 4; mt++) {
        const int row0 = m0 + wr * 64 + mt * 16 + g;
        const int row1 = row0 + 8;
        float inv0 = 1.0f, inv1 = 1.0f;
        if (DENOM) {
            inv0 = 1.0f / denom[(long)z * dstride + row0];
            inv1 = 1.0f / denom[(long)z * dstride + row1];
        }
#pragma unroll
        for (int nt = 0; nt < 8; nt++) {
            const int col = n0 + wc * 64 + nt * 8 + 2 * t;
            float bv0 = 0.0f, bv1 = 0.0f;
            if (BIAS) { bv0 = bias[col]; bv1 = bias[col + 1]; }
            float v0 = acc[mt][nt][0] + bv0;
            float v1 = acc[mt][nt][1] + bv1;
            float v2 = acc[mt][nt][2] + bv0;
            float v3 = acc[mt][nt][3] + bv1;
            if (DENOM) { v0 *= inv0; v1 *= inv0; v2 *= inv1; v3 *= inv1; }
            if (RELU) {
                v0 = fmaxf(v0, 0.0f); v1 = fmaxf(v1, 0.0f);
                v2 = fmaxf(v2, 0.0f); v3 = fmaxf(v3, 0.0f);
            }
            *(float2*)&C[(long)row0 * N + col] = make_float2(v0, v1);
            *(float2*)&C[(long)row1 * N + col] = make_float2(v2, v3);
        }
    }
}

// ---------------- small guarded SGEMM (FFN1 only: M=32) ----------------------
template<bool TRANSB, bool BIAS, bool RELU>
__global__ __launch_bounds__(256) void sgemm_small(
    const float* __restrict__ A, const float* __restrict__ Bm, float* __restrict__ C,
    int M, int N, int K, const float* __restrict__ bias)
{
    __shared__ float As[16][68];
    __shared__ float Bs[16][68];
    const int m0 = blockIdx.y * 64, n0 = blockIdx.x * 64;
    const int tid = threadIdx.x;
    const int tx = tid & 15, ty = tid >> 4;
    float acc[4][4];
#pragma unroll
    for (int i = 0; i < 4; i++)
#pragma unroll
        for (int j = 0; j < 4; j++) acc[i][j] = 0.0f;
    const int arow = tid >> 2, akq = (tid & 3) * 4;
    for (int k0 = 0; k0 < K; k0 += 16) {
        float4 av = make_float4(0.f,0.f,0.f,0.f);
        if (m0 + arow < M)
            av = *(const float4*)&A[(long)(m0 + arow) * K + k0 + akq];
        As[akq+0][arow]=av.x; As[akq+1][arow]=av.y;
        As[akq+2][arow]=av.z; As[akq+3][arow]=av.w;
        if (!TRANSB) {
            const int kr = tid >> 4, nq = (tid & 15) * 4;
            float4 bv = make_float4(0.f,0.f,0.f,0.f);
            if (n0 + nq < N)
                bv = *(const float4*)&Bm[(long)(k0+kr)*N + n0 + nq];
            Bs[kr][nq+0]=bv.x; Bs[kr][nq+1]=bv.y; Bs[kr][nq+2]=bv.z; Bs[kr][nq+3]=bv.w;
        } else {
            const int nrow = tid >> 2, kq = (tid & 3) * 4;
            float4 bv = make_float4(0.f,0.f,0.f,0.f);
            if (n0 + nrow < N)
                bv = *(const float4*)&Bm[(long)(n0+nrow)*K + k0 + kq];
            Bs[kq+0][nrow]=bv.x; Bs[kq+1][nrow]=bv.y; Bs[kq+2][nrow]=bv.z; Bs[kq+3][nrow]=bv.w;
        }
        __syncthreads();
#pragma unroll
        for (int kk = 0; kk < 16; kk++) {
            float4 a = *(const float4*)&As[kk][ty*4];
            float4 b = *(const float4*)&Bs[kk][tx*4];
            acc[0][0]=fmaf(a.x,b.x,acc[0][0]); acc[0][1]=fmaf(a.x,b.y,acc[0][1]);
            acc[0][2]=fmaf(a.x,b.z,acc[0][2]); acc[0][3]=fmaf(a.x,b.w,acc[0][3]);
            acc[1][0]=fmaf(a.y,b.x,acc[1][0]); acc[1][1]=fmaf(a.y,b.y,acc[1][1]);
            acc[1][2]=fmaf(a.y,b.z,acc[1][2]); acc[1][3]=fmaf(a.y,b.w,acc[1][3]);
            acc[2][0]=fmaf(a.z,b.x,acc[2][0]); acc[2][1]=fmaf(a.z,b.y,acc[2][1]);
            acc[2][2]=fmaf(a.z,b.z,acc[2][2]); acc[2][3]=fmaf(a.z,b.w,acc[2][3]);
            acc[3][0]=fmaf(a.w,b.x,acc[3][0]); acc[3][1]=fmaf(a.w,b.y,acc[3][1]);
            acc[3][2]=fmaf(a.w,b.z,acc[3][2]); acc[3][3]=fmaf(a.w,b.w,acc[3][3]);
        }
        __syncthreads();
    }
#pragma unroll
    for (int i = 0; i < 4; i++) {
        int m = m0 + ty*4 + i;
        if (m >= M) continue;
#pragma unroll
        for (int j = 0; j < 4; j++) {
            int n = n0 + tx*4 + j;
            if (n < N) {
                float v = acc[i][j];
                if (BIAS) v += bias[n];
                if (RELU) v = fmaxf(v, 0.0f);
                C[(long)m * N + n] = v;
            }
        }
    }
}

// ============== fused adjacency: mma scores + register softmax ==============
// Block = (b, 32-row tile), 512 threads, 16 warps; warp w owns S-cols [w*32,+32).
// No score buffer: softmax/head-mean done on mma fragments via shfl + tiny smem.
__global__ __launch_bounds__(512, 1) void adj_kernel(
    const float* __restrict__ qk, const float* __restrict__ fmask,
    float* __restrict__ adj, float* __restrict__ denom)
{
    extern __shared__ float smx[];
    float* sQh   = smx;                  // [32][100]
    float* sQl   = sQh + 3200;
    float* sKh   = sQl + 3200;           // [512][12]
    float* sKl   = sKh + 6144;
    float* sRedA = sKl + 6144;           // [32][16] row-max partials
    float* sRedB = sRedA + 512;          // [32][16] row-sum partials
    float* sFr   = sRedB + 512;          // [32]
    float* sFm   = sFr + 32;             // [512]

    const int b    = blockIdx.y;
    const int r0   = blockIdx.x * 32;
    const int tid  = threadIdx.x;
    const int wid  = tid >> 5;           // 0..15
    const int lane = tid & 31;
    const int g    = lane >> 2;
    const int qt   = lane & 3;

    if (tid < 32)  sFr[tid] = fmask[b * S_ + r0 + tid];
    if (tid < 512) sFm[tid] = fmask[b * S_ + tid];

    float macc[2][4][4];
#pragma unroll
    for (int i = 0; i < 2; i++)
#pragma unroll
        for (int j = 0; j < 4; j++)
#pragma unroll
            for (int e = 0; e < 4; e++) macc[i][j][e] = 0.0f;

    const float rs = 0.10206207261596577f;   // 1/sqrt(96)
    const float* qb = qk + ((long)b * S_ + r0) * QKW;
    const float* kb = qk + (long)b * S_ * QKW + D_;

    float4 pk0, pk1;
    auto ldgK = [&](int h, int ks) {         // one K row per thread (row = tid)
        const float* src = kb + (long)tid * QKW + h * DK_ + ks * 8;
        pk0 = *(const float4*)(src);
        pk1 = *(const float4*)(src + 4);
    };
    auto stsK = [&]() {
        uint4 h0, l0, h1, l1;
        split4(pk0, h0, l0); split4(pk1, h1, l1);
        float* dh = sKh + tid * 12;
        float* dl = sKl + tid * 12;
        *(uint4*)(dh)     = h0; *(uint4*)(dh + 4) = h1;
        *(uint4*)(dl)     = l0; *(uint4*)(dl + 4) = l1;
    };

    ldgK(0, 0);

    for (int h = 0; h < H_; h++) {
        // ---- stage Q (block-shared) ----
        for (int j = tid; j < 32 * 24; j += 512) {
            int row = j / 24, c4 = (j % 24) * 4;
            float4 v = *(const float4*)&qb[(long)row * QKW + h * DK_ + c4];
            uint4 hh, ll; split4(v, hh, ll);
            *(uint4*)&sQh[row * 100 + c4] = hh;
            *(uint4*)&sQl[row * 100 + c4] = ll;
        }
        __syncthreads();

        float sacc[2][4][4];
#pragma unroll
        for (int i = 0; i < 2; i++)
#pragma unroll
            for (int j = 0; j < 4; j++)
#pragma unroll
                for (int e = 0; e < 4; e++) sacc[i][j][e] = 0.0f;

        for (int ks = 0; ks < 12; ks++) {
            stsK();
            if (ks < 11)    ldgK(h, ks + 1);
            else if (h < 7) ldgK(h + 1, 0);
            __syncwarp();
            uint32_t ah[2][4], al[2][4];
#pragma unroll
            for (int mt = 0; mt < 2; mt++) {
                const int ab = (mt * 16 + g) * 100 + ks * 8 + qt;
                ah[mt][0] = __float_as_uint(sQh[ab]);
                ah[mt][1] = __float_as_uint(sQh[ab + 800]);
                ah[mt][2] = __float_as_uint(sQh[ab + 4]);
                ah[mt][3] = __float_as_uint(sQh[ab + 804]);
                al[mt][0] = __float_as_uint(sQl[ab]);
                al[mt][1] = __float_as_uint(sQl[ab + 800]);
                al[mt][2] = __float_as_uint(sQl[ab + 4]);
                al[mt][3] = __float_as_uint(sQl[ab + 804]);
            }
#pragma unroll
            for (int nt = 0; nt < 4; nt++) {
                const int nb = (wid * 32 + nt * 8 + g) * 12 + qt;
                uint32_t bh[2], bl[2];
                bh[0] = __float_as_uint(sKh[nb]);
                bh[1] = __float_as_uint(sKh[nb + 4]);
                bl[0] = __float_as_uint(sKl[nb]);
                bl[1] = __float_as_uint(sKl[nb + 4]);
#pragma unroll
                for (int mt = 0; mt < 2; mt++) {
                    mma_tf32(sacc[mt][nt], ah[mt], bh);
                    mma_tf32(sacc[mt][nt], ah[mt], bl);
                    mma_tf32(sacc[mt][nt], al[mt], bh);
                }
            }
            __syncwarp();
        }

        // ---- scale + mask in registers ----
#pragma unroll
        for (int mt = 0; mt < 2; mt++) {
            const int r1 = mt * 16 + g, r2 = r1 + 8;
            const float f1 = sFr[r1], f2 = sFr[r2];
#pragma unroll
            for (int nt = 0; nt < 4; nt++) {
                const int col = wid * 32 + nt * 8 + 2 * qt;
                const float c0 = sFm[col], c1 = sFm[col + 1];
                float v0 = sacc[mt][nt][0] * rs; if (f1 * c0 == 0.0f) v0 = -1e9f;
                float v1 = sacc[mt][nt][1] * rs; if (f1 * c1 == 0.0f) v1 = -1e9f;
                float v2 = sacc[mt][nt][2] * rs; if (f2 * c0 == 0.0f) v2 = -1e9f;
                float v3 = sacc[mt][nt][3] * rs; if (f2 * c1 == 0.0f) v3 = -1e9f;
                sacc[mt][nt][0] = v0; sacc[mt][nt][1] = v1;
                sacc[mt][nt][2] = v2; sacc[mt][nt][3] = v3;
            }
        }

        // ---- row max: quad shfl + cross-warp smem reduce ----
        float mg[4];   // [mt*2 + half]
#pragma unroll
        for (int mt = 0; mt < 2; mt++) {
#pragma unroll
            for (int hf = 0; hf < 2; hf++) {
                float m = -INFINITY;
#pragma unroll
                for (int nt = 0; nt < 4; nt++) {
                    m = fmaxf(m, sacc[mt][nt][hf * 2]);
                    m = fmaxf(m, sacc[mt][nt][hf * 2 + 1]);
                }
                mg[mt * 2 + hf] = m;
            }
        }
#pragma unroll
        for (int i = 0; i < 4; i++) {
            mg[i] = fmaxf(mg[i], __shfl_xor_sync(0xffffffffu, mg[i], 1));
            mg[i] = fmaxf(mg[i], __shfl_xor_sync(0xffffffffu, mg[i], 2));
        }
        if (qt == 0) {
#pragma unroll
            for (int i = 0; i < 4; i++) {
                int r = (i >> 1) * 16 + g + (i & 1) * 8;
                sRedA[r * 16 + wid] = mg[i];
            }
        }
        __syncthreads();
#pragma unroll
        for (int i = 0; i < 4; i++) {
            int r = (i >> 1) * 16 + g + (i & 1) * 8;
            float m = -INFINITY;
#pragma unroll
            for (int w = 0; w < 16; w++) m = fmaxf(m, sRedA[r * 16 + w]);
            mg[i] = m;
        }

        // ---- exp + row sum ----
        float sums[4] = {0.f, 0.f, 0.f, 0.f};
#pragma unroll
        for (int mt = 0; mt < 2; mt++) {
#pragma unroll
            for (int nt = 0; nt < 4; nt++) {
#pragma unroll
                for (int e = 0; e < 4; e++) {
                    int idx = mt * 2 + (e >> 1);
                    float ev = fast_exp(sacc[mt][nt][e] - mg[idx]);
                    sacc[mt][nt][e] = ev;
                    sums[idx] += ev;
                }
            }
        }
#pragma unroll
        for (int i = 0; i < 4; i++) {
            sums[i] += __shfl_xor_sync(0xffffffffu, sums[i], 1);
            sums[i] += __shfl_xor_sync(0xffffffffu, sums[i], 2);
        }
        if (qt == 0) {
#pragma unroll
            for (int i = 0; i < 4; i++) {
                int r = (i >> 1) * 16 + g + (i & 1) * 8;
                sRedB[r * 16 + wid] = sums[i];
            }
        }
        __syncthreads();
        float scl[4];
#pragma unroll
        for (int i = 0; i < 4; i++) {
            int r = (i >> 1) * 16 + g + (i & 1) * 8;
            float s = 0.0f;
#pragma unroll
            for (int w = 0; w < 16; w++) s += sRedB[r * 16 + w];
            scl[i] = 1.0f / (8.0f * s);
        }

        // ---- accumulate head-mean (fragment layout) ----
#pragma unroll
        for (int mt = 0; mt < 2; mt++)
#pragma unroll
            for (int nt = 0; nt < 4; nt++)
#pragma unroll
                for (int e = 0; e < 4; e++)
                    macc[mt][nt][e] = fmaf(sacc[mt][nt][e], scl[mt * 2 + (e >> 1)],
                                           macc[mt][nt][e]);
    }

    // ---- write adj (diag->1) + denom = 3 - mean_diag, from fragments ----
    const long base = ((long)b * S_ + r0) * S_;
#pragma unroll
    for (int mt = 0; mt < 2; mt++) {
        const int r1 = mt * 16 + g, r2 = r1 + 8;
        const int sg1 = r0 + r1, sg2 = r0 + r2;
#pragma unroll
        for (int nt = 0; nt < 4; nt++) {
            const int col = wid * 32 + nt * 8 + 2 * qt;
            float v0 = macc[mt][nt][0], v1 = macc[mt][nt][1];
            float v2 = macc[mt][nt][2], v3 = macc[mt][nt][3];
            if (col == sg1)     { denom[b * S_ + sg1] = 3.0f - v0; v0 = 1.0f; }
            if (col + 1 == sg1) { denom[b * S_ + sg1] = 3.0f - v1; v1 = 1.0f; }
            if (col == sg2)     { denom[b * S_ + sg2] = 3.0f - v2; v2 = 1.0f; }
            if (col + 1 == sg2) { denom[b * S_ + sg2] = 3.0f - v3; v3 = 1.0f; }
            *(float2*)&adj[base + (long)r1 * S_ + col] = make_float2(v0, v1);
            *(float2*)&adj[base + (long)r2 * S_ + col] = make_float2(v2, v3);
        }
    }
}

// ---------------- aspect max-pool ----------------
__global__ void pool_kernel(const float* __restrict__ tok,
                            const int* __restrict__ am,
                            float* __restrict__ pool)
{
    int d = blockIdx.x * 256 + threadIdx.x;
    int b = blockIdx.y;
    if (d >= D_) return;
    const float* tp = tok + (long)b * S_ * D_;
    const int*   ap = am + b * S_;
    float m = -10000.0f;
    for (int s = 0; s < S_; s++) {
        float v = (ap[s] == 1) ? tp[(long)s * D_ + d] : -10000.0f;
        m = fmaxf(m, v);
    }
    pool[b * D_ + d] = m;
}

// ---------------- FFN2 + output assembly ----------------
__global__ void ffn2_kernel(const float* __restrict__ h,
                            const float* __restrict__ w2,
                            const float* __restrict__ b2,
                            const float* __restrict__ pool,
                            float* __restrict__ out)
{
    int bid = blockIdx.x;
    if (bid < 96) {
        int idx = bid * 256 + threadIdx.x;
        out[B_ * C_ + idx] = pool[idx];
    } else {
        int t = threadIdx.x;
        if (t < B_ * C_) {
            int b = t / C_, c = t % C_;
            const float* hp = h + b * D_;
            const float* wp = w2 + c * D_;
            float s = b2[c];
            for (int d = 0; d < D_; d++) s = fmaf(hp[d], wp[d], s);
            out[b * C_ + c] = s;
        }
    }
}

// ---------------- orchestration ----------------
extern "C" void kernel_launch(void* const* d_in, const int* in_sizes, int n_in,
                              void* d_out, int out_size)
{
    const float* x     = (const float*)d_in[0];
    const float* fmask = (const float*)d_in[1];
    const int*   amask = (const int*)  d_in[2];
    const float* wq    = (const float*)d_in[3];
    const float* wk    = (const float*)d_in[4];
    const float* gw    = (const float*)d_in[5];
    const float* gb    = (const float*)d_in[6];
    const float* w1    = (const float*)d_in[7];
    const float* b1    = (const float*)d_in[8];
    const float* w2    = (const float*)d_in[9];
    const float* b2    = (const float*)d_in[10];
    float* out = (float*)d_out;

    float *pqk, *pwqk, *padj, *pden, *pax, *pt1, *pt2, *ppool, *phid;
    cudaGetSymbolAddress((void**)&pqk,   g_qk);
    cudaGetSymbolAddress((void**)&pwqk,  g_wqk);
    cudaGetSymbolAddress((void**)&padj,  g_adj);
    cudaGetSymbolAddress((void**)&pden,  g_den);
    cudaGetSymbolAddress((void**)&pax,   g_ax);
    cudaGetSymbolAddress((void**)&pt1,   g_t1);
    cudaGetSymbolAddress((void**)&pt2,   g_t2);
    cudaGetSymbolAddress((void**)&ppool, g_pool);
    cudaGetSymbolAddress((void**)&phid,  g_hid);

    cudaFuncSetAttribute(gemm_mma<false,false,false,false>,
                         cudaFuncAttributeMaxDynamicSharedMemorySize, MMA_SMEM);
    cudaFuncSetAttribute(gemm_mma<true,true,true,true>,
                         cudaFuncAttributeMaxDynamicSharedMemorySize, MMA_SMEM);

    // 0) concat/transpose weights
    wqk_transpose<<<(H_*D_*DK_ + 255) / 256, 256>>>(wq, wk, pwqk);

    // 1) fused Q|K projection: [16384 x 768] @ [768 x 1536]
    gemm_mma<false,false,false,false><<<dim3(QKW/128, (B_*S_)/128, 1), 128, MMA_SMEM>>>(
        x, pwqk, pqk, B_*S_, QKW, D_, 0L, 0L, 0L, nullptr, nullptr, 0);

    // 2) fused scores(mma) -> register softmax -> head-mean -> adjacency
    {
        const int smem = (3200*2 + 6144*2 + 512*2 + 32 + 512) * 4;  // 81024 B
        cudaFuncSetAttribute(adj_kernel,
                             cudaFuncAttributeMaxDynamicSharedMemorySize, smem);
        adj_kernel<<<dim3(16, B_), 512, smem>>>(pqk, fmask, padj, pden);
    }

    // 3) GCN layers
    {
        dim3 g(D_/128, S_/128, B_);   // (6, 4, 32)
        gemm_mma<false,false,false,false><<<g, 128, MMA_SMEM>>>(
            padj, x, pax, S_, D_, S_,
            (long)S_*S_, (long)S_*D_, (long)S_*D_, nullptr, nullptr, 0);
        gemm_mma<true,true,true,true><<<g, 128, MMA_SMEM>>>(
            pax, gw, pt1, S_, D_, D_,
            (long)S_*D_, 0L, (long)S_*D_, gb, pden, S_);
        gemm_mma<false,false,false,false><<<g, 128, MMA_SMEM>>>(
            padj, pt1, pax, S_, D_, S_,
            (long)S_*S_, (long)S_*D_, (long)S_*D_, nullptr, nullptr, 0);
        gemm_mma<true,true,true,true><<<g, 128, MMA_SMEM>>>(
            pax, gw + (long)D_*D_, pt2, S_, D_, D_,
            (long)S_*D_, 0L, (long)S_*D_, gb + D_, pden, S_);
    }

    // 4) aspect max-pool -> preds
    pool_kernel<<<dim3(3, B_), 256>>>(pt2, amask, ppool);

    // 5) FFN1
    sgemm_small<true,true,true><<<dim3(12, 1, 1), 256>>>(
        ppool, w1, phid, B_, D_, D_, b1);

    // 6) FFN2 + output
    ffn2_kernel<<<97, 256>>>(phid, w2, b2, ppool, out);
}

// round 7
// speedup vs baseline: 1.8557x; 1.0987x over previous
#include <cuda_runtime.h>
#include <math.h>
#include <stdint.h>

#define B_  32
#define S_  512
#define D_  768
#define H_  8
#define DK_ 96
#define C_  3
#define QKW 1536   // fused q|k width

// ---------------- scratch (device globals; no allocs allowed) ----------------
__device__ float g_qk    [(long)B_*S_*QKW];
__device__ float g_wqk   [D_*QKW];
__device__ float g_scores[(long)B_*H_*S_*S_];   // 256 MiB
__device__ float g_adj   [(long)B_*S_*S_];
__device__ float g_den   [B_*S_];
__device__ float g_ax    [B_*S_*D_];
__device__ float g_t1    [B_*S_*D_];
__device__ float g_t2    [B_*S_*D_];
__device__ float g_pool  [B_*D_];
__device__ float g_hid   [B_*D_];

// ---------------- tf32 helpers ----------------
__device__ __forceinline__ void split1(float v, uint32_t& h, uint32_t& l) {
    uint32_t hb, lb;
    asm("cvt.rna.tf32.f32 %0, %1;" : "=r"(hb) : "f"(v));
    float lf = v - __uint_as_float(hb);
    asm("cvt.rna.tf32.f32 %0, %1;" : "=r"(lb) : "f"(lf));
    h = hb; l = lb;
}
__device__ __forceinline__ void split4(float4 v, uint4& h, uint4& l) {
    split1(v.x, h.x, l.x); split1(v.y, h.y, l.y);
    split1(v.z, h.z, l.z); split1(v.w, h.w, l.w);
}
__device__ __forceinline__ void mma_tf32(float* c, const uint32_t* a, const uint32_t* b) {
    asm volatile(
        "mma.sync.aligned.m16n8k8.row.col.f32.tf32.tf32.f32 "
        "{%0,%1,%2,%3}, {%4,%5,%6,%7}, {%8,%9}, {%0,%1,%2,%3};"
        : "+f"(c[0]), "+f"(c[1]), "+f"(c[2]), "+f"(c[3])
        : "r"(a[0]), "r"(a[1]), "r"(a[2]), "r"(a[3]), "r"(b[0]), "r"(b[1]));
}

// ---------------- fast exp ----------------
__device__ __forceinline__ float fast_exp(float x) {
    float y = fmaxf(x * 1.4426950408889634f, -126.0f);
    float t = __fadd_rn(y, 12582912.0f);
    float n = __fsub_rn(t, 12582912.0f);
    float f = __fsub_rn(y, n);
    float p = 0.0013333558f;
    p = fmaf(p, f, 0.0096181291f);
    p = fmaf(p, f, 0.0555041087f);
    p = fmaf(p, f, 0.2402265070f);
    p = fmaf(p, f, 0.6931471806f);
    p = fmaf(p, f, 1.0f);
    int e = (int)n;
    return __int_as_float(__float_as_int(p) + (e << 23));
}

// ---------------- weight concat/transpose ----------------
__global__ void wqk_transpose(const float* __restrict__ wq,
                              const float* __restrict__ wk,
                              float* __restrict__ out)
{
    int idx = blockIdx.x * 256 + threadIdx.x;
    if (idx >= H_ * D_ * DK_) return;
    int h = idx / (D_ * DK_);
    int r = idx % (D_ * DK_);
    int d = r / DK_, j = r % DK_;
    out[(long)d * QKW + h * DK_ + j]       = wq[idx];
    out[(long)d * QKW + D_ + h * DK_ + j]  = wk[idx];
}

// ================= tf32x3 GEMM: 128x128 tile, 4 warps of 64x64, KC=16 =======
// Generalized: leading dims lda/ldb, two-level batch z = zb*hdiv + zh.
// TRANSB: B is [N,K] rows; else [K,N]. M,N %128==0, K%16==0.
#define KP2 20
#define GSZ (128 * KP2)                 // 2560 floats per buffer
#define MMA_SMEM (8 * GSZ * 4)          // 81920 B

template<bool TRANSB, bool BIAS, bool RELU, bool DENOM>
__global__ __launch_bounds__(128, 2) void gemm_mma(
    const float* __restrict__ A, const float* __restrict__ Bm, float* __restrict__ C,
    int M, int N, int K, int lda, int ldb,
    long sA, long hA, long sB, long hB, long sC, int hdiv,
    const float* __restrict__ bias, const float* __restrict__ denom, int dstride)
{
    extern __shared__ float sm[];

    const int tid  = threadIdx.x;
    const int wid  = tid >> 5;
    const int lane = tid & 31;
    const int g    = lane >> 2;
    const int t    = lane & 3;
    const int wr   = wid & 1;
    const int wc   = wid >> 1;

    const int z  = blockIdx.z;
    const int zb = z / hdiv;
    const int zh = z - zb * hdiv;
    A  += (long)zb * sA + (long)zh * hA;
    Bm += (long)zb * sB + (long)zh * hB;
    C  += (long)z * sC;

    const int m0 = blockIdx.y * 128;
    const int n0 = blockIdx.x * 128;

    float acc[4][8][4];
#pragma unroll
    for (int i = 0; i < 4; i++)
#pragma unroll
        for (int j = 0; j < 8; j++)
#pragma unroll
            for (int e = 0; e < 4; e++) acc[i][j][e] = 0.0f;

    float4 pa[4], pb[4];

    auto ldgf = [&](int c) {
        const float* ap = A + (long)(m0 + tid) * lda + c * 16;
#pragma unroll
        for (int i = 0; i < 4; i++) pa[i] = *(const float4*)(ap + i * 4);
        if (TRANSB) {
            const float* bp = Bm + (long)(n0 + tid) * ldb + c * 16;
#pragma unroll
            for (int i = 0; i < 4; i++) pb[i] = *(const float4*)(bp + i * 4);
        } else {
            const float* bp = Bm + (long)(c * 16) * ldb + n0 + tid;
#pragma unroll
            for (int i = 0; i < 4; i++) {
                pb[i].x = bp[(long)(4 * i + 0) * ldb];
                pb[i].y = bp[(long)(4 * i + 1) * ldb];
                pb[i].z = bp[(long)(4 * i + 2) * ldb];
                pb[i].w = bp[(long)(4 * i + 3) * ldb];
            }
        }
    };
    auto stsf = [&](int s) {
        float* dah = sm + s * GSZ + tid * KP2;
        float* dal = sm + (2 + s) * GSZ + tid * KP2;
        float* dbh = sm + (4 + s) * GSZ + tid * KP2;
        float* dbl = sm + (6 + s) * GSZ + tid * KP2;
#pragma unroll
        for (int i = 0; i < 4; i++) {
            uint4 h, l; split4(pa[i], h, l);
            *(uint4*)(dah + i * 4) = h;
            *(uint4*)(dal + i * 4) = l;
        }
#pragma unroll
        for (int i = 0; i < 4; i++) {
            uint4 h, l; split4(pb[i], h, l);
            *(uint4*)(dbh + i * 4) = h;
            *(uint4*)(dbl + i * 4) = l;
        }
    };

    auto compute = [&](int s) {
        const float* aH = sm + s * GSZ;
        const float* aL = sm + (2 + s) * GSZ;
        const float* bH = sm + (4 + s) * GSZ;
        const float* bL = sm + (6 + s) * GSZ;
#pragma unroll
        for (int kt = 0; kt < 2; kt++) {
            uint32_t ah[4][4], al[4][4];
#pragma unroll
            for (int mt = 0; mt < 4; mt++) {
                const int base = (wr * 64 + mt * 16 + g) * KP2 + kt * 8 + t;
                ah[mt][0] = __float_as_uint(aH[base]);
                ah[mt][1] = __float_as_uint(aH[base + 8 * KP2]);
                ah[mt][2] = __float_as_uint(aH[base + 4]);
                ah[mt][3] = __float_as_uint(aH[base + 8 * KP2 + 4]);
                al[mt][0] = __float_as_uint(aL[base]);
                al[mt][1] = __float_as_uint(aL[base + 8 * KP2]);
                al[mt][2] = __float_as_uint(aL[base + 4]);
                al[mt][3] = __float_as_uint(aL[base + 8 * KP2 + 4]);
            }
#pragma unroll
            for (int nt = 0; nt < 8; nt++) {
                const int nb = (wc * 64 + nt * 8 + g) * KP2 + kt * 8 + t;
                uint32_t bh[2], bl[2];
                bh[0] = __float_as_uint(bH[nb]);
                bh[1] = __float_as_uint(bH[nb + 4]);
                bl[0] = __float_as_uint(bL[nb]);
                bl[1] = __float_as_uint(bL[nb + 4]);
#pragma unroll
                for (int mt = 0; mt < 4; mt++) {
                    mma_tf32(acc[mt][nt], ah[mt], bh);
                    mma_tf32(acc[mt][nt], ah[mt], bl);
                    mma_tf32(acc[mt][nt], al[mt], bh);
                }
            }
        }
    };

    const int NC = K >> 4;
    ldgf(0); stsf(0);
    __syncthreads();
    for (int it = 1; it < NC; it++) {
        ldgf(it);
        compute((it - 1) & 1);
        stsf(it & 1);
        __syncthreads();
    }
    compute((NC - 1) & 1);

    // ---- epilogue ----
#pragma unroll
    for (int mt = 0; mt < 4; mt++) {
        const int row0 = m0 + wr * 64 + mt * 16 + g;
        const int row1 = row0 + 8;
        float inv0 = 1.0f, inv1 = 1.0f;
        if (DENOM) {
            inv0 = 1.0f / denom[(long)zb * dstride + row0];
            inv1 = 1.0f / denom[(long)zb * dstride + row1];
        }
#pragma unroll
        for (int nt = 0; nt < 8; nt++) {
            const int col = n0 + wc * 64 + nt * 8 + 2 * t;
            float bv0 = 0.0f, bv1 = 0.0f;
            if (BIAS) { bv0 = bias[col]; bv1 = bias[col + 1]; }
            float v0 = acc[mt][nt][0] + bv0;
            float v1 = acc[mt][nt][1] + bv1;
            float v2 = acc[mt][nt][2] + bv0;
            float v3 = acc[mt][nt][3] + bv1;
            if (DENOM) { v0 *= inv0; v1 *= inv0; v2 *= inv1; v3 *= inv1; }
            if (RELU) {
                v0 = fmaxf(v0, 0.0f); v1 = fmaxf(v1, 0.0f);
                v2 = fmaxf(v2, 0.0f); v3 = fmaxf(v3, 0.0f);
            }
            *(float2*)&C[(long)row0 * N + col] = make_float2(v0, v1);
            *(float2*)&C[(long)row1 * N + col] = make_float2(v2, v3);
        }
    }
}

// ======= streaming softmax + head-mean: scores[B,H,S,S] -> adj, denom =======
// Block = (b, 32 rows). 512 threads, 16 warps; warp handles 2 rows serially.
// Each lane owns 16 columns (4 x float4); full softmax in registers + shfl.
__global__ __launch_bounds__(512, 1) void softmax_mean_kernel(
    const float* __restrict__ scores, const float* __restrict__ fmask,
    float* __restrict__ adj, float* __restrict__ denom)
{
    const int b   = blockIdx.y;
    const int r0  = blockIdx.x * 32;
    const int wid = threadIdx.x >> 5;
    const int lane = threadIdx.x & 31;
    const float rs = 0.10206207261596577f;   // 1/sqrt(96)

    float fmv[16];
#pragma unroll
    for (int c = 0; c < 4; c++) {
        float4 v = *(const float4*)&fmask[b * S_ + c * 128 + lane * 4];
        fmv[c*4+0] = v.x; fmv[c*4+1] = v.y; fmv[c*4+2] = v.z; fmv[c*4+3] = v.w;
    }

#pragma unroll
    for (int rr = 0; rr < 2; rr++) {
        const int i  = r0 + wid * 2 + rr;
        const float fr = fmask[b * S_ + i];
        float acc[16];
#pragma unroll
        for (int e = 0; e < 16; e++) acc[e] = 0.0f;

        for (int h = 0; h < H_; h++) {
            const float* p = scores + ((long)(b * H_ + h) * S_ + i) * S_;
            float ev[16];
#pragma unroll
            for (int c = 0; c < 4; c++) {
                float4 v = *(const float4*)&p[c * 128 + lane * 4];
                ev[c*4+0] = v.x; ev[c*4+1] = v.y; ev[c*4+2] = v.z; ev[c*4+3] = v.w;
            }
            float mx = -INFINITY;
#pragma unroll
            for (int e = 0; e < 16; e++) {
                float vv = (fr * fmv[e] == 0.0f) ? -1e9f : ev[e] * rs;
                ev[e] = vv;
                mx = fmaxf(mx, vv);
            }
            mx = fmaxf(mx, __shfl_xor_sync(0xffffffffu, mx, 1));
            mx = fmaxf(mx, __shfl_xor_sync(0xffffffffu, mx, 2));
            mx = fmaxf(mx, __shfl_xor_sync(0xffffffffu, mx, 4));
            mx = fmaxf(mx, __shfl_xor_sync(0xffffffffu, mx, 8));
            mx = fmaxf(mx, __shfl_xor_sync(0xffffffffu, mx, 16));
            float s = 0.0f;
#pragma unroll
            for (int e = 0; e < 16; e++) {
                float x = fast_exp(ev[e] - mx);
                ev[e] = x;
                s += x;
            }
            s += __shfl_xor_sync(0xffffffffu, s, 1);
            s += __shfl_xor_sync(0xffffffffu, s, 2);
            s += __shfl_xor_sync(0xffffffffu, s, 4);
            s += __shfl_xor_sync(0xffffffffu, s, 8);
            s += __shfl_xor_sync(0xffffffffu, s, 16);
            const float inv = 1.0f / (8.0f * s);
#pragma unroll
            for (int e = 0; e < 16; e++) acc[e] = fmaf(ev[e], inv, acc[e]);
        }

        float* arow = adj + ((long)b * S_ + i) * S_;
#pragma unroll
        for (int c = 0; c < 4; c++) {
            float4 o;
#pragma unroll
            for (int e = 0; e < 4; e++) {
                int j = c * 128 + lane * 4 + e;
                float v = acc[c * 4 + e];
                if (j == i) { denom[b * S_ + i] = 3.0f - v; v = 1.0f; }
                ((float*)&o)[e] = v;
            }
            *(float4*)&arow[c * 128 + lane * 4] = o;
        }
    }
}

// ---------------- small guarded SGEMM (FFN1 only: M=32) ----------------------
template<bool TRANSB, bool BIAS, bool RELU>
__global__ __launch_bounds__(256) void sgemm_small(
    const float* __restrict__ A, const float* __restrict__ Bm, float* __restrict__ C,
    int M, int N, int K, const float* __restrict__ bias)
{
    __shared__ float As[16][68];
    __shared__ float Bs[16][68];
    const int m0 = blockIdx.y * 64, n0 = blockIdx.x * 64;
    const int tid = threadIdx.x;
    const int tx = tid & 15, ty = tid >> 4;
    float acc[4][4];
#pragma unroll
    for (int i = 0; i < 4; i++)
#pragma unroll
        for (int j = 0; j < 4; j++) acc[i][j] = 0.0f;
    const int arow = tid >> 2, akq = (tid & 3) * 4;
    for (int k0 = 0; k0 < K; k0 += 16) {
        float4 av = make_float4(0.f,0.f,0.f,0.f);
        if (m0 + arow < M)
            av = *(const float4*)&A[(long)(m0 + arow) * K + k0 + akq];
        As[akq+0][arow]=av.x; As[akq+1][arow]=av.y;
        As[akq+2][arow]=av.z; As[akq+3][arow]=av.w;
        if (!TRANSB) {
            const int kr = tid >> 4, nq = (tid & 15) * 4;
            float4 bv = make_float4(0.f,0.f,0.f,0.f);
            if (n0 + nq < N)
                bv = *(const float4*)&Bm[(long)(k0+kr)*N + n0 + nq];
            Bs[kr][nq+0]=bv.x; Bs[kr][nq+1]=bv.y; Bs[kr][nq+2]=bv.z; Bs[kr][nq+3]=bv.w;
        } else {
            const int nrow = tid >> 2, kq = (tid & 3) * 4;
            float4 bv = make_float4(0.f,0.f,0.f,0.f);
            if (n0 + nrow < N)
                bv = *(const float4*)&Bm[(long)(n0+nrow)*K + k0 + kq];
            Bs[kq+0][nrow]=bv.x; Bs[kq+1][nrow]=bv.y; Bs[kq+2][nrow]=bv.z; Bs[kq+3][nrow]=bv.w;
        }
        __syncthreads();
#pragma unroll
        for (int kk = 0; kk < 16; kk++) {
            float4 a = *(const float4*)&As[kk][ty*4];
            float4 b = *(const float4*)&Bs[kk][tx*4];
            acc[0][0]=fmaf(a.x,b.x,acc[0][0]); acc[0][1]=fmaf(a.x,b.y,acc[0][1]);
            acc[0][2]=fmaf(a.x,b.z,acc[0][2]); acc[0][3]=fmaf(a.x,b.w,acc[0][3]);
            acc[1][0]=fmaf(a.y,b.x,acc[1][0]); acc[1][1]=fmaf(a.y,b.y,acc[1][1]);
            acc[1][2]=fmaf(a.y,b.z,acc[1][2]); acc[1][3]=fmaf(a.y,b.w,acc[1][3]);
            acc[2][0]=fmaf(a.z,b.x,acc[2][0]); acc[2][1]=fmaf(a.z,b.y,acc[2][1]);
            acc[2][2]=fmaf(a.z,b.z,acc[2][2]); acc[2][3]=fmaf(a.z,b.w,acc[2][3]);
            acc[3][0]=fmaf(a.w,b.x,acc[3][0]); acc[3][1]=fmaf(a.w,b.y,acc[3][1]);
            acc[3][2]=fmaf(a.w,b.z,acc[3][2]); acc[3][3]=fmaf(a.w,b.w,acc[3][3]);
        }
        __syncthreads();
    }
#pragma unroll
    for (int i = 0; i < 4; i++) {
        int m = m0 + ty*4 + i;
        if (m >= M) continue;
#pragma unroll
        for (int j = 0; j < 4; j++) {
            int n = n0 + tx*4 + j;
            if (n < N) {
                float v = acc[i][j];
                if (BIAS) v += bias[n];
                if (RELU) v = fmaxf(v, 0.0f);
                C[(long)m * N + n] = v;
            }
        }
    }
}

// ---------------- aspect max-pool ----------------
__global__ void pool_kernel(const float* __restrict__ tok,
                            const int* __restrict__ am,
                            float* __restrict__ pool)
{
    int d = blockIdx.x * 256 + threadIdx.x;
    int b = blockIdx.y;
    if (d >= D_) return;
    const float* tp = tok + (long)b * S_ * D_;
    const int*   ap = am + b * S_;
    float m = -10000.0f;
    for (int s = 0; s < S_; s++) {
        float v = (ap[s] == 1) ? tp[(long)s * D_ + d] : -10000.0f;
        m = fmaxf(m, v);
    }
    pool[b * D_ + d] = m;
}

// ---------------- FFN2 + output assembly ----------------
__global__ void ffn2_kernel(const float* __restrict__ h,
                            const float* __restrict__ w2,
                            const float* __restrict__ b2,
                            const float* __restrict__ pool,
                            float* __restrict__ out)
{
    int bid = blockIdx.x;
    if (bid < 96) {
        int idx = bid * 256 + threadIdx.x;
        out[B_ * C_ + idx] = pool[idx];
    } else {
        int t = threadIdx.x;
        if (t < B_ * C_) {
            int b = t / C_, c = t % C_;
            const float* hp = h + b * D_;
            const float* wp = w2 + c * D_;
            float s = b2[c];
            for (int d = 0; d < D_; d++) s = fmaf(hp[d], wp[d], s);
            out[b * C_ + c] = s;
        }
    }
}

// ---------------- orchestration ----------------
extern "C" void kernel_launch(void* const* d_in, const int* in_sizes, int n_in,
                              void* d_out, int out_size)
{
    const float* x     = (const float*)d_in[0];
    const float* fmask = (const float*)d_in[1];
    const int*   amask = (const int*)  d_in[2];
    const float* wq    = (const float*)d_in[3];
    const float* wk    = (const float*)d_in[4];
    const float* gw    = (const float*)d_in[5];
    const float* gb    = (const float*)d_in[6];
    const float* w1    = (const float*)d_in[7];
    const float* b1    = (const float*)d_in[8];
    const float* w2    = (const float*)d_in[9];
    const float* b2    = (const float*)d_in[10];
    float* out = (float*)d_out;

    float *pqk, *pwqk, *pscores, *padj, *pden, *pax, *pt1, *pt2, *ppool, *phid;
    cudaGetSymbolAddress((void**)&pqk,    g_qk);
    cudaGetSymbolAddress((void**)&pwqk,   g_wqk);
    cudaGetSymbolAddress((void**)&pscores,g_scores);
    cudaGetSymbolAddress((void**)&padj,   g_adj);
    cudaGetSymbolAddress((void**)&pden,   g_den);
    cudaGetSymbolAddress((void**)&pax,    g_ax);
    cudaGetSymbolAddress((void**)&pt1,    g_t1);
    cudaGetSymbolAddress((void**)&pt2,    g_t2);
    cudaGetSymbolAddress((void**)&ppool,  g_pool);
    cudaGetSymbolAddress((void**)&phid,   g_hid);

    cudaFuncSetAttribute(gemm_mma<false,false,false,false>,
                         cudaFuncAttributeMaxDynamicSharedMemorySize, MMA_SMEM);
    cudaFuncSetAttribute(gemm_mma<true,false,false,false>,
                         cudaFuncAttributeMaxDynamicSharedMemorySize, MMA_SMEM);
    cudaFuncSetAttribute(gemm_mma<true,true,true,true>,
                         cudaFuncAttributeMaxDynamicSharedMemorySize, MMA_SMEM);

    // 0) concat/transpose weights
    wqk_transpose<<<(H_*D_*DK_ + 255) / 256, 256>>>(wq, wk, pwqk);

    // 1) fused Q|K projection: [16384 x 768] @ [768 x 1536]
    gemm_mma<false,false,false,false><<<dim3(QKW/128, (B_*S_)/128, 1), 128, MMA_SMEM>>>(
        x, pwqk, pqk, B_*S_, QKW, D_, D_, QKW,
        0L, 0L, 0L, 0L, 0L, 1, nullptr, nullptr, 0);

    // 2a) scores[b,h] = Q_bh @ K_bh^T  (batched over z = b*8+h, K=96)
    gemm_mma<true,false,false,false><<<dim3(4, 4, B_*H_), 128, MMA_SMEM>>>(
        pqk, pqk + D_, pscores, S_, S_, DK_, QKW, QKW,
        (long)S_*QKW, (long)DK_, (long)S_*QKW, (long)DK_, (long)S_*S_, H_,
        nullptr, nullptr, 0);

    // 2b) streaming softmax + head-mean -> adj, denom
    softmax_mean_kernel<<<dim3(16, B_), 512>>>(pscores, fmask, padj, pden);

    // 3) GCN layers
    {
        dim3 g(D_/128, S_/128, B_);   // (6, 4, 32)
        gemm_mma<false,false,false,false><<<g, 128, MMA_SMEM>>>(
            padj, x, pax, S_, D_, S_, S_, D_,
            (long)S_*S_, 0L, (long)S_*D_, 0L, (long)S_*D_, 1, nullptr, nullptr, 0);
        gemm_mma<true,true,true,true><<<g, 128, MMA_SMEM>>>(
            pax, gw, pt1, S_, D_, D_, D_, D_,
            (long)S_*D_, 0L, 0L, 0L, (long)S_*D_, 1, gb, pden, S_);
        gemm_mma<false,false,false,false><<<g, 128, MMA_SMEM>>>(
            padj, pt1, pax, S_, D_, S_, S_, D_,
            (long)S_*S_, 0L, (long)S_*D_, 0L, (long)S_*D_, 1, nullptr, nullptr, 0);
        gemm_mma<true,true,true,true><<<g, 128, MMA_SMEM>>>(
            pax, gw + (long)D_*D_, pt2, S_, D_, D_, D_, D_,
            (long)S_*D_, 0L, 0L, 0L, (long)S_*D_, 1, gb + D_, pden, S_);
    }

    // 4) aspect max-pool -> preds
    pool_kernel<<<dim3(3, B_), 256>>>(pt2, amask, ppool);

    // 5) FFN1
    sgemm_small<true,true,true><<<dim3(12, 1, 1), 256>>>(
        ppool, w1, phid, B_, D_, D_, b1);

    // 6) FFN2 + output
    ffn2_kernel<<<97, 256>>>(phid, w2, b2, ppool, out);
}

// round 8
// speedup vs baseline: 2.4822x; 1.3376x over previous
#include <cuda_runtime.h>
#include <math.h>
#include <stdint.h>

#define B_  32
#define S_  512
#define D_  768
#define H_  8
#define DK_ 96
#define C_  3
#define QKW 1536   // fused q|k width

// ---------------- scratch (device globals; no allocs allowed) ----------------
__device__ float g_qk    [(long)B_*S_*QKW];
__device__ float g_wqk   [D_*QKW];
__device__ float g_scores[(long)B_*H_*S_*S_];   // 256 MiB
__device__ float g_adj   [(long)B_*S_*S_];
__device__ float g_den   [B_*S_];
__device__ float g_ax    [B_*S_*D_];
__device__ float g_t1    [B_*S_*D_];
__device__ float g_t2    [B_*S_*D_];
__device__ float g_pool  [B_*D_];
__device__ float g_hid   [B_*D_];

// ---------------- bf16x3 helpers ----------------
// hi = truncate-to-bf16 (exact bits), lo = rn-bf16(v - hi). Packed as bf16x2
// with LOW 16 bits = first (even-k) element — consistent for A and B.
__device__ __forceinline__ void bsplit2(float x, float y, uint32_t& h, uint32_t& l) {
    uint32_t bx = __float_as_uint(x), by = __float_as_uint(y);
    h = __byte_perm(bx, by, 0x7632);          // {y_hi16, x_hi16}
    float lx = x - __uint_as_float(bx & 0xFFFF0000u);
    float ly = y - __uint_as_float(by & 0xFFFF0000u);
    asm("cvt.rn.bf16x2.f32 %0, %1, %2;" : "=r"(l) : "f"(ly), "f"(lx));
}
__device__ __forceinline__ void mma_bf16(float* c, const uint32_t* a, const uint32_t* b) {
    asm volatile(
        "mma.sync.aligned.m16n8k16.row.col.f32.bf16.bf16.f32 "
        "{%0,%1,%2,%3}, {%4,%5,%6,%7}, {%8,%9}, {%0,%1,%2,%3};"
        : "+f"(c[0]), "+f"(c[1]), "+f"(c[2]), "+f"(c[3])
        : "r"(a[0]), "r"(a[1]), "r"(a[2]), "r"(a[3]), "r"(b[0]), "r"(b[1]));
}

// ---------------- fast exp ----------------
__device__ __forceinline__ float fast_exp(float x) {
    float y = fmaxf(x * 1.4426950408889634f, -126.0f);
    float t = __fadd_rn(y, 12582912.0f);
    float n = __fsub_rn(t, 12582912.0f);
    float f = __fsub_rn(y, n);
    float p = 0.0013333558f;
    p = fmaf(p, f, 0.0096181291f);
    p = fmaf(p, f, 0.0555041087f);
    p = fmaf(p, f, 0.2402265070f);
    p = fmaf(p, f, 0.6931471806f);
    p = fmaf(p, f, 1.0f);
    int e = (int)n;
    return __int_as_float(__float_as_int(p) + (e << 23));
}

// ---------------- weight concat/transpose ----------------
__global__ void wqk_transpose(const float* __restrict__ wq,
                              const float* __restrict__ wk,
                              float* __restrict__ out)
{
    int idx = blockIdx.x * 256 + threadIdx.x;
    if (idx >= H_ * D_ * DK_) return;
    int h = idx / (D_ * DK_);
    int r = idx % (D_ * DK_);
    int d = r / DK_, j = r % DK_;
    out[(long)d * QKW + h * DK_ + j]       = wq[idx];
    out[(long)d * QKW + D_ + h * DK_ + j]  = wk[idx];
}

// ========= bf16x3 GEMM: 128x128 tile, 4 warps of 64x64, KC=16 (one k16) =====
// Generalized: leading dims lda/ldb, two-level batch z = zb*hdiv + zh.
// TRANSB: B is [N,K] rows; else [K,N]. M,N %128==0, K%16==0.
// smem rows: 8 uint32 (16 bf16) + 4 pad = 12 words -> conflict-free frag loads.
#define SRW 12
#define TSZ (128 * SRW)                 // uint32 per (matrix,prec,buffer)
#define MMA_SMEM (8 * TSZ * 4)          // 49152 B

template<bool TRANSB, bool BIAS, bool RELU, bool DENOM>
__global__ __launch_bounds__(128, 2) void gemm_mma(
    const float* __restrict__ A, const float* __restrict__ Bm, float* __restrict__ C,
    int M, int N, int K, int lda, int ldb,
    long sA, long hA, long sB, long hB, long sC, int hdiv,
    const float* __restrict__ bias, const float* __restrict__ denom, int dstride)
{
    extern __shared__ uint32_t sm[];

    const int tid  = threadIdx.x;
    const int wid  = tid >> 5;
    const int lane = tid & 31;
    const int g    = lane >> 2;
    const int t    = lane & 3;
    const int wr   = wid & 1;
    const int wc   = wid >> 1;

    const int z  = blockIdx.z;
    const int zb = z / hdiv;
    const int zh = z - zb * hdiv;
    A  += (long)zb * sA + (long)zh * hA;
    Bm += (long)zb * sB + (long)zh * hB;
    C  += (long)z * sC;

    const int m0 = blockIdx.y * 128;
    const int n0 = blockIdx.x * 128;

    float acc[4][8][4];
#pragma unroll
    for (int i = 0; i < 4; i++)
#pragma unroll
        for (int j = 0; j < 8; j++)
#pragma unroll
            for (int e = 0; e < 4; e++) acc[i][j][e] = 0.0f;

    float4 pa[4], pb[4];

    auto ldgf = [&](int c) {
        const float* ap = A + (long)(m0 + tid) * lda + c * 16;
#pragma unroll
        for (int i = 0; i < 4; i++) pa[i] = *(const float4*)(ap + i * 4);
        if (TRANSB) {
            const float* bp = Bm + (long)(n0 + tid) * ldb + c * 16;
#pragma unroll
            for (int i = 0; i < 4; i++) pb[i] = *(const float4*)(bp + i * 4);
        } else {
            const float* bp = Bm + (long)(c * 16) * ldb + n0 + tid;
#pragma unroll
            for (int i = 0; i < 4; i++) {
                pb[i].x = bp[(long)(4 * i + 0) * ldb];
                pb[i].y = bp[(long)(4 * i + 1) * ldb];
                pb[i].z = bp[(long)(4 * i + 2) * ldb];
                pb[i].w = bp[(long)(4 * i + 3) * ldb];
            }
        }
    };
    auto stsf = [&](int s) {
        uint32_t hw[8], lw[8];
#pragma unroll
        for (int i = 0; i < 4; i++) {
            bsplit2(pa[i].x, pa[i].y, hw[2*i],   lw[2*i]);
            bsplit2(pa[i].z, pa[i].w, hw[2*i+1], lw[2*i+1]);
        }
        uint32_t* dah = sm + s * TSZ + tid * SRW;
        uint32_t* dal = sm + (2 + s) * TSZ + tid * SRW;
        *(uint4*)(dah)     = make_uint4(hw[0], hw[1], hw[2], hw[3]);
        *(uint4*)(dah + 4) = make_uint4(hw[4], hw[5], hw[6], hw[7]);
        *(uint4*)(dal)     = make_uint4(lw[0], lw[1], lw[2], lw[3]);
        *(uint4*)(dal + 4) = make_uint4(lw[4], lw[5], lw[6], lw[7]);
#pragma unroll
        for (int i = 0; i < 4; i++) {
            bsplit2(pb[i].x, pb[i].y, hw[2*i],   lw[2*i]);
            bsplit2(pb[i].z, pb[i].w, hw[2*i+1], lw[2*i+1]);
        }
        uint32_t* dbh = sm + (4 + s) * TSZ + tid * SRW;
        uint32_t* dbl = sm + (6 + s) * TSZ + tid * SRW;
        *(uint4*)(dbh)     = make_uint4(hw[0], hw[1], hw[2], hw[3]);
        *(uint4*)(dbh + 4) = make_uint4(hw[4], hw[5], hw[6], hw[7]);
        *(uint4*)(dbl)     = make_uint4(lw[0], lw[1], lw[2], lw[3]);
        *(uint4*)(dbl + 4) = make_uint4(lw[4], lw[5], lw[6], lw[7]);
    };

    auto compute = [&](int s) {
        const uint32_t* aH = sm + s * TSZ;
        const uint32_t* aL = sm + (2 + s) * TSZ;
        const uint32_t* bH = sm + (4 + s) * TSZ;
        const uint32_t* bL = sm + (6 + s) * TSZ;
        uint32_t ah[4][4], al[4][4];
#pragma unroll
        for (int mt = 0; mt < 4; mt++) {
            const int base = (wr * 64 + mt * 16 + g) * SRW + t;
            ah[mt][0] = aH[base];
            ah[mt][1] = aH[base + 8 * SRW];
            ah[mt][2] = aH[base + 4];
            ah[mt][3] = aH[base + 8 * SRW + 4];
            al[mt][0] = aL[base];
            al[mt][1] = aL[base + 8 * SRW];
            al[mt][2] = aL[base + 4];
            al[mt][3] = aL[base + 8 * SRW + 4];
        }
#pragma unroll
        for (int nt = 0; nt < 8; nt++) {
            const int nb = (wc * 64 + nt * 8 + g) * SRW + t;
            uint32_t bh[2], bl[2];
            bh[0] = bH[nb];
            bh[1] = bH[nb + 4];
            bl[0] = bL[nb];
            bl[1] = bL[nb + 4];
#pragma unroll
            for (int mt = 0; mt < 4; mt++) {
                mma_bf16(acc[mt][nt], ah[mt], bh);
                mma_bf16(acc[mt][nt], ah[mt], bl);
                mma_bf16(acc[mt][nt], al[mt], bh);
            }
        }
    };

    const int NC = K >> 4;
    ldgf(0); stsf(0);
    __syncthreads();
    for (int it = 1; it < NC; it++) {
        ldgf(it);
        compute((it - 1) & 1);
        stsf(it & 1);
        __syncthreads();
    }
    compute((NC - 1) & 1);

    // ---- epilogue ----
#pragma unroll
    for (int mt = 0; mt < 4; mt++) {
        const int row0 = m0 + wr * 64 + mt * 16 + g;
        const int row1 = row0 + 8;
        float inv0 = 1.0f, inv1 = 1.0f;
        if (DENOM) {
            inv0 = 1.0f / denom[(long)zb * dstride + row0];
            inv1 = 1.0f / denom[(long)zb * dstride + row1];
        }
#pragma unroll
        for (int nt = 0; nt < 8; nt++) {
            const int col = n0 + wc * 64 + nt * 8 + 2 * t;
            float bv0 = 0.0f, bv1 = 0.0f;
            if (BIAS) { bv0 = bias[col]; bv1 = bias[col + 1]; }
            float v0 = acc[mt][nt][0] + bv0;
            float v1 = acc[mt][nt][1] + bv1;
            float v2 = acc[mt][nt][2] + bv0;
            float v3 = acc[mt][nt][3] + bv1;
            if (DENOM) { v0 *= inv0; v1 *= inv0; v2 *= inv1; v3 *= inv1; }
            if (RELU) {
                v0 = fmaxf(v0, 0.0f); v1 = fmaxf(v1, 0.0f);
                v2 = fmaxf(v2, 0.0f); v3 = fmaxf(v3, 0.0f);
            }
            *(float2*)&C[(long)row0 * N + col] = make_float2(v0, v1);
            *(float2*)&C[(long)row1 * N + col] = make_float2(v2, v3);
        }
    }
}

// ======= streaming softmax + head-mean: scores[B,H,S,S] -> adj, denom =======
__global__ __launch_bounds__(512, 1) void softmax_mean_kernel(
    const float* __restrict__ scores, const float* __restrict__ fmask,
    float* __restrict__ adj, float* __restrict__ denom)
{
    const int b   = blockIdx.y;
    const int r0  = blockIdx.x * 32;
    const int wid = threadIdx.x >> 5;
    const int lane = threadIdx.x & 31;
    const float rs = 0.10206207261596577f;   // 1/sqrt(96)

    float fmv[16];
#pragma unroll
    for (int c = 0; c < 4; c++) {
        float4 v = *(const float4*)&fmask[b * S_ + c * 128 + lane * 4];
        fmv[c*4+0] = v.x; fmv[c*4+1] = v.y; fmv[c*4+2] = v.z; fmv[c*4+3] = v.w;
    }

#pragma unroll
    for (int rr = 0; rr < 2; rr++) {
        const int i  = r0 + wid * 2 + rr;
        const float fr = fmask[b * S_ + i];
        float acc[16];
#pragma unroll
        for (int e = 0; e < 16; e++) acc[e] = 0.0f;

        for (int h = 0; h < H_; h++) {
            const float* p = scores + ((long)(b * H_ + h) * S_ + i) * S_;
            float ev[16];
#pragma unroll
            for (int c = 0; c < 4; c++) {
                float4 v = *(const float4*)&p[c * 128 + lane * 4];
                ev[c*4+0] = v.x; ev[c*4+1] = v.y; ev[c*4+2] = v.z; ev[c*4+3] = v.w;
            }
            float mx = -INFINITY;
#pragma unroll
            for (int e = 0; e < 16; e++) {
                float vv = (fr * fmv[e] == 0.0f) ? -1e9f : ev[e] * rs;
                ev[e] = vv;
                mx = fmaxf(mx, vv);
            }
            mx = fmaxf(mx, __shfl_xor_sync(0xffffffffu, mx, 1));
            mx = fmaxf(mx, __shfl_xor_sync(0xffffffffu, mx, 2));
            mx = fmaxf(mx, __shfl_xor_sync(0xffffffffu, mx, 4));
            mx = fmaxf(mx, __shfl_xor_sync(0xffffffffu, mx, 8));
            mx = fmaxf(mx, __shfl_xor_sync(0xffffffffu, mx, 16));
            float s = 0.0f;
#pragma unroll
            for (int e = 0; e < 16; e++) {
                float x = fast_exp(ev[e] - mx);
                ev[e] = x;
                s += x;
            }
            s += __shfl_xor_sync(0xffffffffu, s, 1);
            s += __shfl_xor_sync(0xffffffffu, s, 2);
            s += __shfl_xor_sync(0xffffffffu, s, 4);
            s += __shfl_xor_sync(0xffffffffu, s, 8);
            s += __shfl_xor_sync(0xffffffffu, s, 16);
            const float inv = 1.0f / (8.0f * s);
#pragma unroll
            for (int e = 0; e < 16; e++) acc[e] = fmaf(ev[e], inv, acc[e]);
        }

        float* arow = adj + ((long)b * S_ + i) * S_;
#pragma unroll
        for (int c = 0; c < 4; c++) {
            float4 o;
#pragma unroll
            for (int e = 0; e < 4; e++) {
                int j = c * 128 + lane * 4 + e;
                float v = acc[c * 4 + e];
                if (j == i) { denom[b * S_ + i] = 3.0f - v; v = 1.0f; }
                ((float*)&o)[e] = v;
            }
            *(float4*)&arow[c * 128 + lane * 4] = o;
        }
    }
}

// ---------------- small guarded SGEMM (FFN1 only: M=32) ----------------------
template<bool TRANSB, bool BIAS, bool RELU>
__global__ __launch_bounds__(256) void sgemm_small(
    const float* __restrict__ A, const float* __restrict__ Bm, float* __restrict__ C,
    int M, int N, int K, const float* __restrict__ bias)
{
    __shared__ float As[16][68];
    __shared__ float Bs[16][68];
    const int m0 = blockIdx.y * 64, n0 = blockIdx.x * 64;
    const int tid = threadIdx.x;
    const int tx = tid & 15, ty = tid >> 4;
    float acc[4][4];
#pragma unroll
    for (int i = 0; i < 4; i++)
#pragma unroll
        for (int j = 0; j < 4; j++) acc[i][j] = 0.0f;
    const int arow = tid >> 2, akq = (tid & 3) * 4;
    for (int k0 = 0; k0 < K; k0 += 16) {
        float4 av = make_float4(0.f,0.f,0.f,0.f);
        if (m0 + arow < M)
            av = *(const float4*)&A[(long)(m0 + arow) * K + k0 + akq];
        As[akq+0][arow]=av.x; As[akq+1][arow]=av.y;
        As[akq+2][arow]=av.z; As[akq+3][arow]=av.w;
        if (!TRANSB) {
            const int kr = tid >> 4, nq = (tid & 15) * 4;
            float4 bv = make_float4(0.f,0.f,0.f,0.f);
            if (n0 + nq < N)
                bv = *(const float4*)&Bm[(long)(k0+kr)*N + n0 + nq];
            Bs[kr][nq+0]=bv.x; Bs[kr][nq+1]=bv.y; Bs[kr][nq+2]=bv.z; Bs[kr][nq+3]=bv.w;
        } else {
            const int nrow = tid >> 2, kq = (tid & 3) * 4;
            float4 bv = make_float4(0.f,0.f,0.f,0.f);
            if (n0 + nrow < N)
                bv = *(const float4*)&Bm[(long)(n0+nrow)*K + k0 + kq];
            Bs[kq+0][nrow]=bv.x; Bs[kq+1][nrow]=bv.y; Bs[kq+2][nrow]=bv.z; Bs[kq+3][nrow]=bv.w;
        }
        __syncthreads();
#pragma unroll
        for (int kk = 0; kk < 16; kk++) {
            float4 a = *(const float4*)&As[kk][ty*4];
            float4 b = *(const float4*)&Bs[kk][tx*4];
            acc[0][0]=fmaf(a.x,b.x,acc[0][0]); acc[0][1]=fmaf(a.x,b.y,acc[0][1]);
            acc[0][2]=fmaf(a.x,b.z,acc[0][2]); acc[0][3]=fmaf(a.x,b.w,acc[0][3]);
            acc[1][0]=fmaf(a.y,b.x,acc[1][0]); acc[1][1]=fmaf(a.y,b.y,acc[1][1]);
            acc[1][2]=fmaf(a.y,b.z,acc[1][2]); acc[1][3]=fmaf(a.y,b.w,acc[1][3]);
            acc[2][0]=fmaf(a.z,b.x,acc[2][0]); acc[2][1]=fmaf(a.z,b.y,acc[2][1]);
            acc[2][2]=fmaf(a.z,b.z,acc[2][2]); acc[2][3]=fmaf(a.z,b.w,acc[2][3]);
            acc[3][0]=fmaf(a.w,b.x,acc[3][0]); acc[3][1]=fmaf(a.w,b.y,acc[3][1]);
            acc[3][2]=fmaf(a.w,b.z,acc[3][2]); acc[3][3]=fmaf(a.w,b.w,acc[3][3]);
        }
        __syncthreads();
    }
#pragma unroll
    for (int i = 0; i < 4; i++) {
        int m = m0 + ty*4 + i;
        if (m >= M) continue;
#pragma unroll
        for (int j = 0; j < 4; j++) {
            int n = n0 + tx*4 + j;
            if (n < N) {
                float v = acc[i][j];
                if (BIAS) v += bias[n];
                if (RELU) v = fmaxf(v, 0.0f);
                C[(long)m * N + n] = v;
            }
        }
    }
}

// ---------------- aspect max-pool ----------------
__global__ void pool_kernel(const float* __restrict__ tok,
                            const int* __restrict__ am,
                            float* __restrict__ pool)
{
    int d = blockIdx.x * 256 + threadIdx.x;
    int b = blockIdx.y;
    if (d >= D_) return;
    const float* tp = tok + (long)b * S_ * D_;
    const int*   ap = am + b * S_;
    float m = -10000.0f;
#pragma unroll 8
    for (int s = 0; s < S_; s++) {
        float v = (ap[s] == 1) ? tp[(long)s * D_ + d] : -10000.0f;
        m = fmaxf(m, v);
    }
    pool[b * D_ + d] = m;
}

// ---------------- FFN2 + output assembly ----------------
__global__ void ffn2_kernel(const float* __restrict__ h,
                            const float* __restrict__ w2,
                            const float* __restrict__ b2,
                            const float* __restrict__ pool,
                            float* __restrict__ out)
{
    int bid = blockIdx.x;
    if (bid < 96) {
        int idx = bid * 256 + threadIdx.x;
        out[B_ * C_ + idx] = pool[idx];
    } else {
        int t = threadIdx.x;
        if (t < B_ * C_) {
            int b = t / C_, c = t % C_;
            const float* hp = h + b * D_;
            const float* wp = w2 + c * D_;
            float s = b2[c];
            for (int d = 0; d < D_; d++) s = fmaf(hp[d], wp[d], s);
            out[b * C_ + c] = s;
        }
    }
}

// ---------------- orchestration ----------------
extern "C" void kernel_launch(void* const* d_in, const int* in_sizes, int n_in,
                              void* d_out, int out_size)
{
    const float* x     = (const float*)d_in[0];
    const float* fmask = (const float*)d_in[1];
    const int*   amask = (const int*)  d_in[2];
    const float* wq    = (const float*)d_in[3];
    const float* wk    = (const float*)d_in[4];
    const float* gw    = (const float*)d_in[5];
    const float* gb    = (const float*)d_in[6];
    const float* w1    = (const float*)d_in[7];
    const float* b1    = (const float*)d_in[8];
    const float* w2    = (const float*)d_in[9];
    const float* b2    = (const float*)d_in[10];
    float* out = (float*)d_out;

    float *pqk, *pwqk, *pscores, *padj, *pden, *pax, *pt1, *pt2, *ppool, *phid;
    cudaGetSymbolAddress((void**)&pqk,    g_qk);
    cudaGetSymbolAddress((void**)&pwqk,   g_wqk);
    cudaGetSymbolAddress((void**)&pscores,g_scores);
    cudaGetSymbolAddress((void**)&padj,   g_adj);
    cudaGetSymbolAddress((void**)&pden,   g_den);
    cudaGetSymbolAddress((void**)&pax,    g_ax);
    cudaGetSymbolAddress((void**)&pt1,    g_t1);
    cudaGetSymbolAddress((void**)&pt2,    g_t2);
    cudaGetSymbolAddress((void**)&ppool,  g_pool);
    cudaGetSymbolAddress((void**)&phid,   g_hid);

    cudaFuncSetAttribute(gemm_mma<false,false,false,false>,
                         cudaFuncAttributeMaxDynamicSharedMemorySize, MMA_SMEM);
    cudaFuncSetAttribute(gemm_mma<true,false,false,false>,
                         cudaFuncAttributeMaxDynamicSharedMemorySize, MMA_SMEM);
    cudaFuncSetAttribute(gemm_mma<true,true,true,true>,
                         cudaFuncAttributeMaxDynamicSharedMemorySize, MMA_SMEM);

    // 0) concat/transpose weights
    wqk_transpose<<<(H_*D_*DK_ + 255) / 256, 256>>>(wq, wk, pwqk);

    // 1) fused Q|K projection: [16384 x 768] @ [768 x 1536]
    gemm_mma<false,false,false,false><<<dim3(QKW/128, (B_*S_)/128, 1), 128, MMA_SMEM>>>(
        x, pwqk, pqk, B_*S_, QKW, D_, D_, QKW,
        0L, 0L, 0L, 0L, 0L, 1, nullptr, nullptr, 0);

    // 2a) scores[b,h] = Q_bh @ K_bh^T  (batched over z = b*8+h, K=96)
    gemm_mma<true,false,false,false><<<dim3(4, 4, B_*H_), 128, MMA_SMEM>>>(
        pqk, pqk + D_, pscores, S_, S_, DK_, QKW, QKW,
        (long)S_*QKW, (long)DK_, (long)S_*QKW, (long)DK_, (long)S_*S_, H_,
        nullptr, nullptr, 0);

    // 2b) streaming softmax + head-mean -> adj, denom
    softmax_mean_kernel<<<dim3(16, B_), 512>>>(pscores, fmask, padj, pden);

    // 3) GCN layers
    {
        dim3 g(D_/128, S_/128, B_);   // (6, 4, 32)
        gemm_mma<false,false,false,false><<<g, 128, MMA_SMEM>>>(
            padj, x, pax, S_, D_, S_, S_, D_,
            (long)S_*S_, 0L, (long)S_*D_, 0L, (long)S_*D_, 1, nullptr, nullptr, 0);
        gemm_mma<true,true,true,true><<<g, 128, MMA_SMEM>>>(
            pax, gw, pt1, S_, D_, D_, D_, D_,
            (long)S_*D_, 0L, 0L, 0L, (long)S_*D_, 1, gb, pden, S_);
        gemm_mma<false,false,false,false><<<g, 128, MMA_SMEM>>>(
            padj, pt1, pax, S_, D_, S_, S_, D_,
            (long)S_*S_, 0L, (long)S_*D_, 0L, (long)S_*D_, 1, nullptr, nullptr, 0);
        gemm_mma<true,true,true,true><<<g, 128, MMA_SMEM>>>(
            pax, gw + (long)D_*D_, pt2, S_, D_, D_, D_, D_,
            (long)S_*D_, 0L, 0L, 0L, (long)S_*D_, 1, gb + D_, pden, S_);
    }

    // 4) aspect max-pool -> preds
    pool_kernel<<<dim3(3, B_), 256>>>(pt2, amask, ppool);

    // 5) FFN1
    sgemm_small<true,true,true><<<dim3(12, 1, 1), 256>>>(
        ppool, w1, phid, B_, D_, D_, b1);

    // 6) FFN2 + output
    ffn2_kernel<<<97, 256>>>(phid, w2, b2, ppool, out);
}